// round 1
// baseline (speedup 1.0000x reference)
#include <cuda_runtime.h>
#include <math.h>

#define MTOT   8192       // B*S
#define DMODEL 768
#define NHEADS 12
#define DHEAD  64
#define DMLP   3072
#define SEQ    1024
#define BATCH  8
#define QKVW   (3*DMODEL) // 2304

// ---------------- scratch (static __device__, no allocation) ----------------
__device__ float g_xn  [MTOT*DMODEL];   // ln1 output
__device__ float g_wqkv[DMODEL*QKVW];   // packed [d, h*64+e | +768 | +1536]
__device__ float g_bqkv[QKVW];
__device__ float g_qkv [MTOT*QKVW];     // fused QKV projection output
__device__ float g_z   [MTOT*DMODEL];   // attention output (pre O-proj)
__device__ float g_mid [MTOT*DMODEL];   // resid_mid
__device__ float g_xn2 [MTOT*DMODEL];   // ln2 output
__device__ float g_hid [MTOT*DMLP];     // MLP hidden

// ---------------- helpers ----------------
__device__ __forceinline__ float gelu_new_f(float x) {
    float x3 = x * x * x;
    float t  = tanhf(0.7978845608028654f * (x + 0.044715f * x3));
    return 0.5f * x * (1.0f + t);
}

// ---------------- weight pack: W_{Q,K,V}[h,d,e] -> B[d, 3*768] ----------------
__global__ void pack_wqkv_kernel(const float* __restrict__ WQ,
                                 const float* __restrict__ WK,
                                 const float* __restrict__ WV) {
    int idx = blockIdx.x * 256 + threadIdx.x;        // over 768*768
    if (idx >= DMODEL * DMODEL) return;
    int d = idx / DMODEL;
    int c = idx % DMODEL;                             // c = h*64 + e
    int h = c >> 6, e = c & 63;
    int src = (h * DMODEL + d) * DHEAD + e;
    g_wqkv[d * QKVW + c]              = WQ[src];
    g_wqkv[d * QKVW + DMODEL + c]     = WK[src];
    g_wqkv[d * QKVW + 2 * DMODEL + c] = WV[src];
}

__global__ void pack_bqkv_kernel(const float* __restrict__ bQ,
                                 const float* __restrict__ bK,
                                 const float* __restrict__ bV) {
    int i = threadIdx.x + blockIdx.x * 256;
    if (i >= QKVW) return;
    g_bqkv[i] = (i < DMODEL) ? bQ[i] : (i < 2 * DMODEL ? bK[i - DMODEL] : bV[i - 2 * DMODEL]);
}

// ---------------- layernorm: one block per row ----------------
__global__ __launch_bounds__(256)
void ln_kernel(const float* __restrict__ x, const float* __restrict__ w,
               const float* __restrict__ b, float* __restrict__ y) {
    __shared__ float ws[8], wq[8], stats[2];
    int row = blockIdx.x;
    int tid = threadIdx.x;
    const float* xr = x + (size_t)row * DMODEL;
    float v0 = xr[tid], v1 = xr[tid + 256], v2 = xr[tid + 512];
    float s  = v0 + v1 + v2;
    float sq = v0 * v0 + v1 * v1 + v2 * v2;
#pragma unroll
    for (int o = 16; o > 0; o >>= 1) {
        s  += __shfl_xor_sync(0xffffffffu, s,  o);
        sq += __shfl_xor_sync(0xffffffffu, sq, o);
    }
    int warp = tid >> 5, lane = tid & 31;
    if (lane == 0) { ws[warp] = s; wq[warp] = sq; }
    __syncthreads();
    if (tid == 0) {
        float ts = 0.f, tq = 0.f;
#pragma unroll
        for (int i = 0; i < 8; i++) { ts += ws[i]; tq += wq[i]; }
        float mean = ts * (1.0f / DMODEL);
        float var  = tq * (1.0f / DMODEL) - mean * mean;
        stats[0] = mean;
        stats[1] = rsqrtf(var + 1e-5f);
    }
    __syncthreads();
    float mean = stats[0], rstd = stats[1];
    float* yr = y + (size_t)row * DMODEL;
    yr[tid]       = (v0 - mean) * rstd * w[tid]       + b[tid];
    yr[tid + 256] = (v1 - mean) * rstd * w[tid + 256] + b[tid + 256];
    yr[tid + 512] = (v2 - mean) * rstd * w[tid + 512] + b[tid + 512];
}

// ---------------- GEMM: C[M,N] = A[M,K] @ B[K,N] (+bias)(+gelu)(+resid) -----
// BM=128, BN=64, BK=16, 256 threads, 8x4 microtile.
// EPI: 0 = bias, 1 = bias+gelu, 2 = bias+resid
template <int EPI>
__global__ __launch_bounds__(256)
void gemm_kernel(const float* __restrict__ A, const float* __restrict__ B,
                 const float* __restrict__ bias, const float* __restrict__ R,
                 float* __restrict__ C, int N, int K) {
    __shared__ float As[16][128];
    __shared__ float Bs[16][64];
    int tid  = threadIdx.x;
    int row0 = blockIdx.y * 128;
    int col0 = blockIdx.x * 64;
    int ty = tid >> 4, tx = tid & 15;

    int arow = tid >> 2;           // 0..63
    int akq  = (tid & 3) * 4;      // 0,4,8,12
    int brow = tid >> 4;           // 0..15
    int bcol = (tid & 15) * 4;

    float acc[8][4];
#pragma unroll
    for (int i = 0; i < 8; i++)
#pragma unroll
        for (int j = 0; j < 4; j++) acc[i][j] = 0.f;

    for (int k0 = 0; k0 < K; k0 += 16) {
        float4 a0 = *(const float4*)&A[(size_t)(row0 + arow)      * K + k0 + akq];
        float4 a1 = *(const float4*)&A[(size_t)(row0 + arow + 64) * K + k0 + akq];
        As[akq + 0][arow] = a0.x; As[akq + 1][arow] = a0.y;
        As[akq + 2][arow] = a0.z; As[akq + 3][arow] = a0.w;
        As[akq + 0][arow + 64] = a1.x; As[akq + 1][arow + 64] = a1.y;
        As[akq + 2][arow + 64] = a1.z; As[akq + 3][arow + 64] = a1.w;
        float4 bv = *(const float4*)&B[(size_t)(k0 + brow) * N + col0 + bcol];
        *(float4*)&Bs[brow][bcol] = bv;
        __syncthreads();
#pragma unroll
        for (int kk = 0; kk < 16; kk++) {
            float4 av0 = *(const float4*)&As[kk][ty * 8];
            float4 av1 = *(const float4*)&As[kk][ty * 8 + 4];
            float4 bb  = *(const float4*)&Bs[kk][tx * 4];
            float a[8] = {av0.x, av0.y, av0.z, av0.w, av1.x, av1.y, av1.z, av1.w};
            float bv4[4] = {bb.x, bb.y, bb.z, bb.w};
#pragma unroll
            for (int i = 0; i < 8; i++)
#pragma unroll
                for (int j = 0; j < 4; j++) acc[i][j] = fmaf(a[i], bv4[j], acc[i][j]);
        }
        __syncthreads();
    }

    float4 b4 = *(const float4*)&bias[col0 + tx * 4];
#pragma unroll
    for (int i = 0; i < 8; i++) {
        int r = row0 + ty * 8 + i;
        float4 v;
        v.x = acc[i][0] + b4.x; v.y = acc[i][1] + b4.y;
        v.z = acc[i][2] + b4.z; v.w = acc[i][3] + b4.w;
        if (EPI == 1) {
            v.x = gelu_new_f(v.x); v.y = gelu_new_f(v.y);
            v.z = gelu_new_f(v.z); v.w = gelu_new_f(v.w);
        }
        if (EPI == 2) {
            float4 rr = *(const float4*)&R[(size_t)r * N + col0 + tx * 4];
            v.x += rr.x; v.y += rr.y; v.z += rr.z; v.w += rr.w;
        }
        *(float4*)&C[(size_t)r * N + col0 + tx * 4] = v;
    }
}

// ---------------- flash attention (causal), 64-row Q tiles ----------------
// grid: (16 q-tiles, 12 heads, 8 batch), 256 threads
__global__ __launch_bounds__(256)
void attn_kernel(const float* __restrict__ qkv, float* __restrict__ z) {
    extern __shared__ float sm[];
    float* Qt   = sm;               // [e][i]   4096
    float* Kt   = sm + 4096;        // [e][j]   4096
    float* Vs   = sm + 8192;        // [j][d]   4096
    float* SP   = sm + 12288;       // S[i][j] then P^T[j][i]
    float* mrow = sm + 16384;       // 64
    float* lrow = mrow + 64;        // 64
    float* arow = lrow + 64;        // 64

    int tid = threadIdx.x;
    int qt = blockIdx.x, h = blockIdx.y, b = blockIdx.z;
    int q0 = qt * 64;
    const float* base = qkv + (size_t)b * SEQ * QKVW;

    int lr = tid >> 4;      // 0..15 (row-within-16)
    int lq = tid & 15;      // float4 column group
    const float scale = 0.125f;  // 1/sqrt(64)

#pragma unroll
    for (int r = 0; r < 4; r++) {
        int i = lr + r * 16;
        float4 q4 = *(const float4*)&base[(size_t)(q0 + i) * QKVW + h * DHEAD + lq * 4];
        Qt[(lq * 4 + 0) * 64 + i] = q4.x * scale;
        Qt[(lq * 4 + 1) * 64 + i] = q4.y * scale;
        Qt[(lq * 4 + 2) * 64 + i] = q4.z * scale;
        Qt[(lq * 4 + 3) * 64 + i] = q4.w * scale;
    }
    if (tid < 64) { mrow[tid] = -INFINITY; lrow[tid] = 0.f; }

    float acc[4][4];
#pragma unroll
    for (int i = 0; i < 4; i++)
#pragma unroll
        for (int j = 0; j < 4; j++) acc[i][j] = 0.f;

    int ty = tid >> 4, tx = tid & 15;
    int rowi = tid >> 2;     // softmax: 4 threads per row
    int part = tid & 3;

    for (int kt = 0; kt <= qt; kt++) {
        int k0 = kt * 64;
        __syncthreads();
        // load K (transposed) and V tiles
#pragma unroll
        for (int r = 0; r < 4; r++) {
            int j = lr + r * 16;
            float4 k4 = *(const float4*)&base[(size_t)(k0 + j) * QKVW + DMODEL + h * DHEAD + lq * 4];
            Kt[(lq * 4 + 0) * 64 + j] = k4.x;
            Kt[(lq * 4 + 1) * 64 + j] = k4.y;
            Kt[(lq * 4 + 2) * 64 + j] = k4.z;
            Kt[(lq * 4 + 3) * 64 + j] = k4.w;
            float4 v4 = *(const float4*)&base[(size_t)(k0 + j) * QKVW + 2 * DMODEL + h * DHEAD + lq * 4];
            *(float4*)&Vs[j * 64 + lq * 4] = v4;
        }
        __syncthreads();

        // S = Q K^T (64x64), 4x4 microtile per thread
        float s[4][4];
#pragma unroll
        for (int i = 0; i < 4; i++)
#pragma unroll
            for (int j = 0; j < 4; j++) s[i][j] = 0.f;
#pragma unroll 8
        for (int e = 0; e < 64; e++) {
            float4 a  = *(const float4*)&Qt[e * 64 + ty * 4];
            float4 bb = *(const float4*)&Kt[e * 64 + tx * 4];
            float av[4] = {a.x, a.y, a.z, a.w};
            float bv[4] = {bb.x, bb.y, bb.z, bb.w};
#pragma unroll
            for (int i = 0; i < 4; i++)
#pragma unroll
                for (int j = 0; j < 4; j++) s[i][j] = fmaf(av[i], bv[j], s[i][j]);
        }
#pragma unroll
        for (int i = 0; i < 4; i++)
#pragma unroll
            for (int j = 0; j < 4; j++)
                SP[(ty * 4 + i) * 64 + tx * 4 + j] = s[i][j];
        __syncthreads();

        // online softmax: each group of 4 threads owns one row
        float p[16];
        float mold = mrow[rowi];
        float mx = mold;
#pragma unroll
        for (int u = 0; u < 16; u++) {
            int j = part * 16 + u;
            float v = SP[rowi * 64 + j];
            p[u] = (k0 + j > q0 + rowi) ? -INFINITY : v;
            mx = fmaxf(mx, p[u]);
        }
        mx = fmaxf(mx, __shfl_xor_sync(0xffffffffu, mx, 1));
        mx = fmaxf(mx, __shfl_xor_sync(0xffffffffu, mx, 2));
        float sum = 0.f;
#pragma unroll
        for (int u = 0; u < 16; u++) {
            float pe = __expf(p[u] - mx);   // -inf -> 0
            p[u] = pe;
            sum += pe;
        }
        sum += __shfl_xor_sync(0xffffffffu, sum, 1);
        sum += __shfl_xor_sync(0xffffffffu, sum, 2);
        float alpha = __expf(mold - mx);
        if (part == 0) {
            mrow[rowi] = mx;
            lrow[rowi] = lrow[rowi] * alpha + sum;
            arow[rowi] = alpha;
        }
        __syncthreads();
        // write P transposed into the same buffer
#pragma unroll
        for (int u = 0; u < 16; u++)
            SP[(part * 16 + u) * 64 + rowi] = p[u];
        __syncthreads();

        // rescale O accumulator, then O += P^T-layout @ V
        float al[4];
#pragma unroll
        for (int i = 0; i < 4; i++) al[i] = arow[ty * 4 + i];
#pragma unroll
        for (int i = 0; i < 4; i++)
#pragma unroll
            for (int j = 0; j < 4; j++) acc[i][j] *= al[i];
#pragma unroll 8
        for (int j = 0; j < 64; j++) {
            float4 a = *(const float4*)&SP[j * 64 + ty * 4];
            float4 v = *(const float4*)&Vs[j * 64 + tx * 4];
            float av[4] = {a.x, a.y, a.z, a.w};
            float vv[4] = {v.x, v.y, v.z, v.w};
#pragma unroll
            for (int i = 0; i < 4; i++)
#pragma unroll
                for (int d = 0; d < 4; d++) acc[i][d] = fmaf(av[i], vv[d], acc[i][d]);
        }
    }

    // final normalize + store z[b, q, h, e]
#pragma unroll
    for (int i = 0; i < 4; i++) {
        int gi = ty * 4 + i;
        float inv = 1.0f / lrow[gi];
        float4 o;
        o.x = acc[i][0] * inv; o.y = acc[i][1] * inv;
        o.z = acc[i][2] * inv; o.w = acc[i][3] * inv;
        *(float4*)&z[((size_t)b * SEQ + q0 + gi) * DMODEL + h * DHEAD + tx * 4] = o;
    }
}

// ---------------- launch ----------------
extern "C" void kernel_launch(void* const* d_in, const int* in_sizes, int n_in,
                              void* d_out, int out_size) {
    const float* resid_pre = (const float*)d_in[0];
    const float* WQ  = (const float*)d_in[1];
    const float* WK  = (const float*)d_in[2];
    const float* WV  = (const float*)d_in[3];
    const float* WO  = (const float*)d_in[4];
    const float* bQ  = (const float*)d_in[5];
    const float* bK  = (const float*)d_in[6];
    const float* bV  = (const float*)d_in[7];
    const float* bO  = (const float*)d_in[8];
    const float* ln1w = (const float*)d_in[9];
    const float* ln1b = (const float*)d_in[10];
    const float* ln2w = (const float*)d_in[11];
    const float* ln2b = (const float*)d_in[12];
    const float* Win  = (const float*)d_in[13];
    const float* bin  = (const float*)d_in[14];
    const float* Wout = (const float*)d_in[15];
    const float* bout = (const float*)d_in[16];
    float* out = (float*)d_out;

    float *p_xn, *p_wqkv, *p_bqkv, *p_qkv, *p_z, *p_mid, *p_xn2, *p_hid;
    cudaGetSymbolAddress((void**)&p_xn,   g_xn);
    cudaGetSymbolAddress((void**)&p_wqkv, g_wqkv);
    cudaGetSymbolAddress((void**)&p_bqkv, g_bqkv);
    cudaGetSymbolAddress((void**)&p_qkv,  g_qkv);
    cudaGetSymbolAddress((void**)&p_z,    g_z);
    cudaGetSymbolAddress((void**)&p_mid,  g_mid);
    cudaGetSymbolAddress((void**)&p_xn2,  g_xn2);
    cudaGetSymbolAddress((void**)&p_hid,  g_hid);

    static const int ATTN_SMEM = (4 * 4096 + 3 * 64) * (int)sizeof(float);
    cudaFuncSetAttribute(attn_kernel, cudaFuncAttributeMaxDynamicSharedMemorySize, ATTN_SMEM);

    // 1) pack fused QKV weights/bias
    pack_wqkv_kernel<<<(DMODEL * DMODEL + 255) / 256, 256>>>(WQ, WK, WV);
    pack_bqkv_kernel<<<(QKVW + 255) / 256, 256>>>(bQ, bK, bV);

    // 2) LN1
    ln_kernel<<<MTOT, 256>>>(resid_pre, ln1w, ln1b, p_xn);

    // 3) fused QKV projection: [8192,768] @ [768,2304]
    gemm_kernel<0><<<dim3(QKVW / 64, MTOT / 128), 256>>>(p_xn, p_wqkv, p_bqkv, nullptr, p_qkv, QKVW, DMODEL);

    // 4) causal flash attention
    attn_kernel<<<dim3(SEQ / 64, NHEADS, BATCH), 256, ATTN_SMEM>>>(p_qkv, p_z);

    // 5) O projection + residual: resid_mid = resid_pre + z @ W_O + b_O
    gemm_kernel<2><<<dim3(DMODEL / 64, MTOT / 128), 256>>>(p_z, WO, bO, resid_pre, p_mid, DMODEL, DMODEL);

    // 6) LN2
    ln_kernel<<<MTOT, 256>>>(p_mid, ln2w, ln2b, p_xn2);

    // 7) MLP in + GELU: [8192,768] @ [768,3072]
    gemm_kernel<1><<<dim3(DMLP / 64, MTOT / 128), 256>>>(p_xn2, Win, bin, nullptr, p_hid, DMLP, DMODEL);

    // 8) MLP out + residual: out = resid_mid + hidden @ W_out + b_out
    gemm_kernel<2><<<dim3(DMODEL / 64, MTOT / 128), 256>>>(p_hid, Wout, bout, p_mid, out, DMODEL, DMLP);
}

// round 4
// speedup vs baseline: 3.5489x; 3.5489x over previous
#include <cuda_runtime.h>
#include <cuda_bf16.h>
#include <math.h>
#include <stdint.h>

#define MTOT   8192
#define DMODEL 768
#define NHEADS 12
#define DHEAD  64
#define DMLP   3072
#define SEQ    1024
#define BATCH  8
#define QKVW   (3*DMODEL)

// ---------------- scratch ----------------
__device__ __align__(256) __nv_bfloat16 g_xn_hi [MTOT*DMODEL];
__device__ __align__(256) __nv_bfloat16 g_xn_lo [MTOT*DMODEL];
__device__ __align__(256) __nv_bfloat16 g_xn2_hi[MTOT*DMODEL];
__device__ __align__(256) __nv_bfloat16 g_xn2_lo[MTOT*DMODEL];
__device__ __align__(256) __nv_bfloat16 g_z_hi  [MTOT*DMODEL];
__device__ __align__(256) __nv_bfloat16 g_z_lo  [MTOT*DMODEL];
__device__ __align__(256) __nv_bfloat16 g_hid_hi[(size_t)MTOT*DMLP];
__device__ __align__(256) __nv_bfloat16 g_hid_lo[(size_t)MTOT*DMLP];
__device__ __align__(256) __nv_bfloat16 g_wqkv_hi[QKVW*DMODEL];
__device__ __align__(256) __nv_bfloat16 g_wqkv_lo[QKVW*DMODEL];
__device__ __align__(256) __nv_bfloat16 g_wo_hi [DMODEL*DMODEL];
__device__ __align__(256) __nv_bfloat16 g_wo_lo [DMODEL*DMODEL];
__device__ __align__(256) __nv_bfloat16 g_win_hi[DMODEL*DMLP];
__device__ __align__(256) __nv_bfloat16 g_win_lo[DMODEL*DMLP];
__device__ __align__(256) __nv_bfloat16 g_wout_hi[DMLP*DMODEL];
__device__ __align__(256) __nv_bfloat16 g_wout_lo[DMLP*DMODEL];
__device__ float g_bqkv[QKVW];
__device__ float g_qkv [(size_t)MTOT*QKVW];
__device__ float g_mid [MTOT*DMODEL];

// ---------------- helpers ----------------
__device__ __forceinline__ uint32_t smem_u32(const void* p) {
    uint32_t a;
    asm("{ .reg .u64 t; cvta.to.shared.u64 t, %1; cvt.u32.u64 %0, t; }" : "=r"(a) : "l"(p));
    return a;
}
#define SW128(o) ((o) ^ (((o) >> 3) & 0x70))

__device__ __forceinline__ void cp16(uint32_t dst, const void* src) {
    asm volatile("cp.async.cg.shared.global [%0], [%1], 16;" :: "r"(dst), "l"(src));
}
#define CP_COMMIT() asm volatile("cp.async.commit_group;" ::: "memory")
#define CP_WAIT(n)  asm volatile("cp.async.wait_group %0;" :: "n"(n) : "memory")

#define LDSM4(r0, r1, r2, r3, addr) \
    asm volatile("ldmatrix.sync.aligned.m8n8.x4.shared.b16 {%0,%1,%2,%3},[%4];" \
        : "=r"(r0), "=r"(r1), "=r"(r2), "=r"(r3) : "r"(addr))

#define MMA16816(d, a, b0, b1) \
    asm volatile("mma.sync.aligned.m16n8k16.row.col.f32.bf16.bf16.f32 " \
        "{%0,%1,%2,%3},{%4,%5,%6,%7},{%8,%9},{%0,%1,%2,%3};" \
        : "+f"((d)[0]), "+f"((d)[1]), "+f"((d)[2]), "+f"((d)[3]) \
        : "r"((a)[0]), "r"((a)[1]), "r"((a)[2]), "r"((a)[3]), "r"(b0), "r"(b1))

__device__ __forceinline__ float gelu_new_f(float x) {
    float x3 = x * x * x;
    return 0.5f * x * (1.0f + tanhf(0.7978845608028654f * (x + 0.044715f * x3)));
}
__device__ __forceinline__ void split_bf16(float x, __nv_bfloat16& h, __nv_bfloat16& l) {
    h = __float2bfloat16(x);
    l = __float2bfloat16(x - __bfloat162float(h));
}
__device__ __forceinline__ uint32_t pack_bf162(__nv_bfloat16 a, __nv_bfloat16 b) {
    __nv_bfloat162 t(a, b);
    return *(uint32_t*)&t;
}

// ---------------- weight packing ----------------
__global__ void pack_wqkv_tc(const float* __restrict__ WQ, const float* __restrict__ WK,
                             const float* __restrict__ WV) {
    int idx = blockIdx.x * 256 + threadIdx.x;
    if (idx >= DMODEL * DMODEL) return;
    int d = idx / DMODEL, c = idx % DMODEL;
    int h = c >> 6, e = c & 63;
    int src = (h * DMODEL + d) * DHEAD + e;
    __nv_bfloat16 hi, lo;
    split_bf16(WQ[src], hi, lo);
    g_wqkv_hi[(size_t)c * DMODEL + d] = hi; g_wqkv_lo[(size_t)c * DMODEL + d] = lo;
    split_bf16(WK[src], hi, lo);
    g_wqkv_hi[(size_t)(DMODEL + c) * DMODEL + d] = hi; g_wqkv_lo[(size_t)(DMODEL + c) * DMODEL + d] = lo;
    split_bf16(WV[src], hi, lo);
    g_wqkv_hi[(size_t)(2 * DMODEL + c) * DMODEL + d] = hi; g_wqkv_lo[(size_t)(2 * DMODEL + c) * DMODEL + d] = lo;
}
// src [K][N] row-major -> dst [N][K] bf16 hi/lo
__global__ void pack_transpose(const float* __restrict__ src, __nv_bfloat16* __restrict__ dh,
                               __nv_bfloat16* __restrict__ dl, int K, int N) {
    size_t idx = (size_t)blockIdx.x * 256 + threadIdx.x;
    if (idx >= (size_t)K * N) return;
    int k = (int)(idx / N), n = (int)(idx % N);
    __nv_bfloat16 hi, lo;
    split_bf16(src[idx], hi, lo);
    dh[(size_t)n * K + k] = hi; dl[(size_t)n * K + k] = lo;
}
__global__ void pack_bqkv_kernel(const float* __restrict__ bQ, const float* __restrict__ bK,
                                 const float* __restrict__ bV) {
    int i = threadIdx.x + blockIdx.x * 256;
    if (i >= QKVW) return;
    g_bqkv[i] = (i < DMODEL) ? bQ[i] : (i < 2 * DMODEL ? bK[i - DMODEL] : bV[i - 2 * DMODEL]);
}

// ---------------- layernorm -> bf16 hi/lo ----------------
__global__ __launch_bounds__(256)
void ln_kernel(const float* __restrict__ x, const float* __restrict__ w, const float* __restrict__ b,
               __nv_bfloat16* __restrict__ yh, __nv_bfloat16* __restrict__ yl) {
    __shared__ float ws[8], wq[8], stats[2];
    int row = blockIdx.x, tid = threadIdx.x;
    const float* xr = x + (size_t)row * DMODEL;
    float v0 = xr[tid], v1 = xr[tid + 256], v2 = xr[tid + 512];
    float s = v0 + v1 + v2, sq = v0 * v0 + v1 * v1 + v2 * v2;
#pragma unroll
    for (int o = 16; o > 0; o >>= 1) {
        s  += __shfl_xor_sync(0xffffffffu, s,  o);
        sq += __shfl_xor_sync(0xffffffffu, sq, o);
    }
    if ((tid & 31) == 0) { ws[tid >> 5] = s; wq[tid >> 5] = sq; }
    __syncthreads();
    if (tid == 0) {
        float ts = 0.f, tq = 0.f;
#pragma unroll
        for (int i = 0; i < 8; i++) { ts += ws[i]; tq += wq[i]; }
        float mean = ts * (1.0f / DMODEL);
        float var  = tq * (1.0f / DMODEL) - mean * mean;
        stats[0] = mean; stats[1] = rsqrtf(var + 1e-5f);
    }
    __syncthreads();
    float mean = stats[0], rstd = stats[1];
    size_t base = (size_t)row * DMODEL;
#pragma unroll
    for (int u = 0; u < 3; u++) {
        int c = tid + u * 256;
        float y = ((u == 0 ? v0 : u == 1 ? v1 : v2) - mean) * rstd * w[c] + b[c];
        __nv_bfloat16 hi, lo; split_bf16(y, hi, lo);
        yh[base + c] = hi; yl[base + c] = lo;
    }
}

// ---------------- mma.sync GEMM: C[M,N] = A[M,K] * B[N,K]^T, split-bf16 -----
// 128x128 CTA tile, BK=64, double-buffered cp.async, 8 warps (2x4), 64x32/warp.
// EPI: 0 = bias -> f32 ; 1 = bias+gelu -> bf16 hi/lo ; 2 = bias+resid -> f32
#define GTILE 16384                  // 128 rows x 128 bytes
#define GSTG  (4*GTILE)              // Ahi, Alo, Bhi, Blo
#define GSMEM (1024 + 2*GSTG)

__device__ __forceinline__ void stage_tile(uint32_t sbase, const __nv_bfloat16* src, int K, int tid) {
#pragma unroll
    for (int it = 0; it < 4; it++) {
        int idx = tid + it * 256;
        int row = idx >> 3, seg = idx & 7;
        uint32_t off = (uint32_t)(row * 128 + seg * 16);
        cp16(sbase + SW128(off), src + (size_t)row * K + seg * 8);
    }
}
__device__ __forceinline__ void stage_chunk(uint32_t tb, const __nv_bfloat16* Ah, const __nv_bfloat16* Al,
                                            const __nv_bfloat16* Bh, const __nv_bfloat16* Bl,
                                            int k0, int K, int tid) {
    stage_tile(tb,             Ah + k0, K, tid);
    stage_tile(tb + GTILE,     Al + k0, K, tid);
    stage_tile(tb + 2 * GTILE, Bh + k0, K, tid);
    stage_tile(tb + 3 * GTILE, Bl + k0, K, tid);
    CP_COMMIT();
}

template <int EPI>
__global__ __launch_bounds__(256, 1)
void gemm_mma(const __nv_bfloat16* __restrict__ Ahi, const __nv_bfloat16* __restrict__ Alo,
              const __nv_bfloat16* __restrict__ Bhi, const __nv_bfloat16* __restrict__ Blo,
              const float* __restrict__ bias, const float* __restrict__ R,
              float* __restrict__ C, __nv_bfloat16* __restrict__ Chi, __nv_bfloat16* __restrict__ Clo,
              int N, int K, int NC) {
    extern __shared__ char smraw[];
    uint32_t sb = (smem_u32(smraw) + 1023) & ~1023u;
    int tid = threadIdx.x;
    int row0 = blockIdx.y * 128, col0 = blockIdx.x * 128;
    int wid = tid >> 5, lane = tid & 31;
    int wm = (wid >> 2) * 64, wn = (wid & 3) * 32;

    const __nv_bfloat16* Ah = Ahi + (size_t)row0 * K;
    const __nv_bfloat16* Al = Alo + (size_t)row0 * K;
    const __nv_bfloat16* Bh = Bhi + (size_t)col0 * K;
    const __nv_bfloat16* Bl = Blo + (size_t)col0 * K;

    stage_chunk(sb,        Ah, Al, Bh, Bl, 0,  K, tid);
    stage_chunk(sb + GSTG, Ah, Al, Bh, Bl, 64, K, tid);

    float acc[4][4][4];
#pragma unroll
    for (int mi = 0; mi < 4; mi++)
#pragma unroll
        for (int ni = 0; ni < 4; ni++)
#pragma unroll
            for (int q = 0; q < 4; q++) acc[mi][ni][q] = 0.f;

    // ldmatrix lane address components
    int ar = lane & 15, ahalf = lane >> 4;                  // A: row in m16, k-half
    int brow = (lane & 7) + ((lane >> 4) << 3);             // B: row in n16
    int bhalf = (lane >> 3) & 1;                            // B: k-half

    for (int i = 0; i < NC; i++) {
        if (i < NC - 1) CP_WAIT(1); else CP_WAIT(0);
        __syncthreads();
        uint32_t tb = sb + (uint32_t)(i & 1) * GSTG;
#pragma unroll
        for (int ks = 0; ks < 4; ks++) {
            uint32_t ahr[4][4], alr[4][4], bhr[2][4], blr[2][4];
#pragma unroll
            for (int mi = 0; mi < 4; mi++) {
                uint32_t off = (uint32_t)((wm + mi * 16 + ar) * 128 + ks * 32 + ahalf * 16);
                uint32_t sw = SW128(off);
                LDSM4(ahr[mi][0], ahr[mi][1], ahr[mi][2], ahr[mi][3], tb + sw);
                LDSM4(alr[mi][0], alr[mi][1], alr[mi][2], alr[mi][3], tb + GTILE + sw);
            }
#pragma unroll
            for (int nb = 0; nb < 2; nb++) {
                uint32_t off = (uint32_t)((wn + nb * 16 + brow) * 128 + ks * 32 + bhalf * 16);
                uint32_t sw = SW128(off);
                LDSM4(bhr[nb][0], bhr[nb][1], bhr[nb][2], bhr[nb][3], tb + 2 * GTILE + sw);
                LDSM4(blr[nb][0], blr[nb][1], blr[nb][2], blr[nb][3], tb + 3 * GTILE + sw);
            }
#pragma unroll
            for (int mi = 0; mi < 4; mi++)
#pragma unroll
                for (int ni = 0; ni < 4; ni++) {
                    int nb = ni >> 1, p = (ni & 1) * 2;
                    MMA16816(acc[mi][ni], ahr[mi], bhr[nb][p], bhr[nb][p + 1]);
                    MMA16816(acc[mi][ni], ahr[mi], blr[nb][p], blr[nb][p + 1]);
                    MMA16816(acc[mi][ni], alr[mi], bhr[nb][p], bhr[nb][p + 1]);
                }
        }
        __syncthreads();
        if (i + 2 < NC)
            stage_chunk(sb + (uint32_t)(i & 1) * GSTG, Ah, Al, Bh, Bl, (i + 2) * 64, K, tid);
    }

    // epilogue: each thread owns 2x2 per mma tile
#pragma unroll
    for (int mi = 0; mi < 4; mi++) {
#pragma unroll
        for (int ni = 0; ni < 4; ni++) {
            int r = row0 + wm + mi * 16 + (lane >> 2);
            int c = col0 + wn + ni * 8 + (lane & 3) * 2;
            float b0 = bias[c], b1 = bias[c + 1];
#pragma unroll
            for (int half = 0; half < 2; half++) {
                int rr = r + half * 8;
                float v0 = acc[mi][ni][2 * half]     + b0;
                float v1 = acc[mi][ni][2 * half + 1] + b1;
                if (EPI == 1) {
                    v0 = gelu_new_f(v0); v1 = gelu_new_f(v1);
                    __nv_bfloat16 h0, l0, h1, l1;
                    split_bf16(v0, h0, l0); split_bf16(v1, h1, l1);
                    *(uint32_t*)&Chi[(size_t)rr * N + c] = pack_bf162(h0, h1);
                    *(uint32_t*)&Clo[(size_t)rr * N + c] = pack_bf162(l0, l1);
                } else {
                    if (EPI == 2) {
                        float2 rv = *(const float2*)&R[(size_t)rr * N + c];
                        v0 += rv.x; v1 += rv.y;
                    }
                    *(float2*)&C[(size_t)rr * N + c] = make_float2(v0, v1);
                }
            }
        }
    }
}

// ---------------- flash attention (fp32), epilogue -> bf16 hi/lo ----------------
__global__ __launch_bounds__(256)
void attn_kernel(const float* __restrict__ qkv, __nv_bfloat16* __restrict__ zh,
                 __nv_bfloat16* __restrict__ zl) {
    extern __shared__ float sm[];
    float* Qt = sm;
    float* Kt = sm + 4096;
    float* Vs = sm + 8192;
    float* SP = sm + 12288;
    float* mrow = sm + 16384;
    float* lrow = mrow + 64;
    float* arow = lrow + 64;

    int tid = threadIdx.x;
    int qt = blockIdx.x, h = blockIdx.y, b = blockIdx.z;
    int q0 = qt * 64;
    const float* base = qkv + (size_t)b * SEQ * QKVW;

    int lr = tid >> 4, lq = tid & 15;
    const float scale = 0.125f;

#pragma unroll
    for (int r = 0; r < 4; r++) {
        int i = lr + r * 16;
        float4 q4 = *(const float4*)&base[(size_t)(q0 + i) * QKVW + h * DHEAD + lq * 4];
        Qt[(lq * 4 + 0) * 64 + i] = q4.x * scale;
        Qt[(lq * 4 + 1) * 64 + i] = q4.y * scale;
        Qt[(lq * 4 + 2) * 64 + i] = q4.z * scale;
        Qt[(lq * 4 + 3) * 64 + i] = q4.w * scale;
    }
    if (tid < 64) { mrow[tid] = -INFINITY; lrow[tid] = 0.f; }

    float acc[4][4];
#pragma unroll
    for (int i = 0; i < 4; i++)
#pragma unroll
        for (int j = 0; j < 4; j++) acc[i][j] = 0.f;

    int ty = tid >> 4, tx = tid & 15;
    int rowi = tid >> 2, part = tid & 3;

    for (int kt = 0; kt <= qt; kt++) {
        int k0 = kt * 64;
        __syncthreads();
#pragma unroll
        for (int r = 0; r < 4; r++) {
            int j = lr + r * 16;
            float4 k4 = *(const float4*)&base[(size_t)(k0 + j) * QKVW + DMODEL + h * DHEAD + lq * 4];
            Kt[(lq * 4 + 0) * 64 + j] = k4.x;
            Kt[(lq * 4 + 1) * 64 + j] = k4.y;
            Kt[(lq * 4 + 2) * 64 + j] = k4.z;
            Kt[(lq * 4 + 3) * 64 + j] = k4.w;
            float4 v4 = *(const float4*)&base[(size_t)(k0 + j) * QKVW + 2 * DMODEL + h * DHEAD + lq * 4];
            *(float4*)&Vs[j * 64 + lq * 4] = v4;
        }
        __syncthreads();

        float s[4][4];
#pragma unroll
        for (int i = 0; i < 4; i++)
#pragma unroll
            for (int j = 0; j < 4; j++) s[i][j] = 0.f;
#pragma unroll 8
        for (int e = 0; e < 64; e++) {
            float4 a  = *(const float4*)&Qt[e * 64 + ty * 4];
            float4 bb = *(const float4*)&Kt[e * 64 + tx * 4];
            float av[4] = {a.x, a.y, a.z, a.w};
            float bv[4] = {bb.x, bb.y, bb.z, bb.w};
#pragma unroll
            for (int i = 0; i < 4; i++)
#pragma unroll
                for (int j = 0; j < 4; j++) s[i][j] = fmaf(av[i], bv[j], s[i][j]);
        }
#pragma unroll
        for (int i = 0; i < 4; i++)
#pragma unroll
            for (int j = 0; j < 4; j++)
                SP[(ty * 4 + i) * 64 + tx * 4 + j] = s[i][j];
        __syncthreads();

        float p[16];
        float mold = mrow[rowi];
        float mx = mold;
#pragma unroll
        for (int u = 0; u < 16; u++) {
            int j = part * 16 + u;
            float v = SP[rowi * 64 + j];
            p[u] = (k0 + j > q0 + rowi) ? -INFINITY : v;
            mx = fmaxf(mx, p[u]);
        }
        mx = fmaxf(mx, __shfl_xor_sync(0xffffffffu, mx, 1));
        mx = fmaxf(mx, __shfl_xor_sync(0xffffffffu, mx, 2));
        float sum = 0.f;
#pragma unroll
        for (int u = 0; u < 16; u++) {
            float pe = __expf(p[u] - mx);
            p[u] = pe; sum += pe;
        }
        sum += __shfl_xor_sync(0xffffffffu, sum, 1);
        sum += __shfl_xor_sync(0xffffffffu, sum, 2);
        float alpha = __expf(mold - mx);
        if (part == 0) {
            mrow[rowi] = mx;
            lrow[rowi] = lrow[rowi] * alpha + sum;
            arow[rowi] = alpha;
        }
        __syncthreads();
#pragma unroll
        for (int u = 0; u < 16; u++)
            SP[(part * 16 + u) * 64 + rowi] = p[u];
        __syncthreads();

        float al[4];
#pragma unroll
        for (int i = 0; i < 4; i++) al[i] = arow[ty * 4 + i];
#pragma unroll
        for (int i = 0; i < 4; i++)
#pragma unroll
            for (int j = 0; j < 4; j++) acc[i][j] *= al[i];
#pragma unroll 8
        for (int j = 0; j < 64; j++) {
            float4 a = *(const float4*)&SP[j * 64 + ty * 4];
            float4 v = *(const float4*)&Vs[j * 64 + tx * 4];
            float av[4] = {a.x, a.y, a.z, a.w};
            float vv[4] = {v.x, v.y, v.z, v.w};
#pragma unroll
            for (int i = 0; i < 4; i++)
#pragma unroll
                for (int d = 0; d < 4; d++) acc[i][d] = fmaf(av[i], vv[d], acc[i][d]);
        }
    }

#pragma unroll
    for (int i = 0; i < 4; i++) {
        int gi = ty * 4 + i;
        float inv = 1.0f / lrow[gi];
        size_t off = ((size_t)b * SEQ + q0 + gi) * DMODEL + h * DHEAD + tx * 4;
        uint32_t hs[2], ls[2];
#pragma unroll
        for (int q = 0; q < 2; q++) {
            float o0 = acc[i][2 * q] * inv, o1 = acc[i][2 * q + 1] * inv;
            __nv_bfloat16 h0, l0, h1, l1;
            split_bf16(o0, h0, l0); split_bf16(o1, h1, l1);
            hs[q] = pack_bf162(h0, h1); ls[q] = pack_bf162(l0, l1);
        }
        *(uint2*)&zh[off] = make_uint2(hs[0], hs[1]);
        *(uint2*)&zl[off] = make_uint2(ls[0], ls[1]);
    }
}

// ---------------- launch ----------------
extern "C" void kernel_launch(void* const* d_in, const int* in_sizes, int n_in,
                              void* d_out, int out_size) {
    const float* resid_pre = (const float*)d_in[0];
    const float* WQ  = (const float*)d_in[1];
    const float* WK  = (const float*)d_in[2];
    const float* WV  = (const float*)d_in[3];
    const float* WO  = (const float*)d_in[4];
    const float* bQ  = (const float*)d_in[5];
    const float* bK  = (const float*)d_in[6];
    const float* bV  = (const float*)d_in[7];
    const float* bO  = (const float*)d_in[8];
    const float* ln1w = (const float*)d_in[9];
    const float* ln1b = (const float*)d_in[10];
    const float* ln2w = (const float*)d_in[11];
    const float* ln2b = (const float*)d_in[12];
    const float* Win  = (const float*)d_in[13];
    const float* bin  = (const float*)d_in[14];
    const float* Wout = (const float*)d_in[15];
    const float* bout = (const float*)d_in[16];
    float* out = (float*)d_out;

    __nv_bfloat16 *p_xnh, *p_xnl, *p_xn2h, *p_xn2l, *p_zh, *p_zl, *p_hidh, *p_hidl;
    __nv_bfloat16 *p_wqh, *p_wql, *p_woh, *p_wol, *p_wih, *p_wil, *p_wouth, *p_woutl;
    float *p_bqkv, *p_qkv, *p_mid;
    cudaGetSymbolAddress((void**)&p_xnh, g_xn_hi);   cudaGetSymbolAddress((void**)&p_xnl, g_xn_lo);
    cudaGetSymbolAddress((void**)&p_xn2h, g_xn2_hi); cudaGetSymbolAddress((void**)&p_xn2l, g_xn2_lo);
    cudaGetSymbolAddress((void**)&p_zh, g_z_hi);     cudaGetSymbolAddress((void**)&p_zl, g_z_lo);
    cudaGetSymbolAddress((void**)&p_hidh, g_hid_hi); cudaGetSymbolAddress((void**)&p_hidl, g_hid_lo);
    cudaGetSymbolAddress((void**)&p_wqh, g_wqkv_hi); cudaGetSymbolAddress((void**)&p_wql, g_wqkv_lo);
    cudaGetSymbolAddress((void**)&p_woh, g_wo_hi);   cudaGetSymbolAddress((void**)&p_wol, g_wo_lo);
    cudaGetSymbolAddress((void**)&p_wih, g_win_hi);  cudaGetSymbolAddress((void**)&p_wil, g_win_lo);
    cudaGetSymbolAddress((void**)&p_wouth, g_wout_hi); cudaGetSymbolAddress((void**)&p_woutl, g_wout_lo);
    cudaGetSymbolAddress((void**)&p_bqkv, g_bqkv);
    cudaGetSymbolAddress((void**)&p_qkv, g_qkv);
    cudaGetSymbolAddress((void**)&p_mid, g_mid);

    static const int ATTN_SMEM = (4 * 4096 + 3 * 64) * (int)sizeof(float);
    cudaFuncSetAttribute(attn_kernel, cudaFuncAttributeMaxDynamicSharedMemorySize, ATTN_SMEM);
    cudaFuncSetAttribute(gemm_mma<0>, cudaFuncAttributeMaxDynamicSharedMemorySize, GSMEM);
    cudaFuncSetAttribute(gemm_mma<1>, cudaFuncAttributeMaxDynamicSharedMemorySize, GSMEM);
    cudaFuncSetAttribute(gemm_mma<2>, cudaFuncAttributeMaxDynamicSharedMemorySize, GSMEM);

    // 1) weight packs
    pack_wqkv_tc<<<(DMODEL * DMODEL + 255) / 256, 256>>>(WQ, WK, WV);
    pack_bqkv_kernel<<<(QKVW + 255) / 256, 256>>>(bQ, bK, bV);
    pack_transpose<<<(DMODEL * DMODEL + 255) / 256, 256>>>(WO,   p_woh,   p_wol,   DMODEL, DMODEL);
    pack_transpose<<<(DMODEL * DMLP  + 255) / 256, 256>>>(Win,  p_wih,   p_wil,   DMODEL, DMLP);
    pack_transpose<<<(DMLP * DMODEL  + 255) / 256, 256>>>(Wout, p_wouth, p_woutl, DMLP,   DMODEL);

    // 2) LN1 -> bf16 hi/lo
    ln_kernel<<<MTOT, 256>>>(resid_pre, ln1w, ln1b, p_xnh, p_xnl);

    // 3) QKV projection [8192,768] x [2304,768]^T -> f32
    gemm_mma<0><<<dim3(QKVW / 128, MTOT / 128), 256, GSMEM>>>(
        p_xnh, p_xnl, p_wqh, p_wql, p_bqkv, nullptr, p_qkv, nullptr, nullptr, QKVW, DMODEL, DMODEL / 64);

    // 4) causal flash attention -> z bf16 hi/lo
    attn_kernel<<<dim3(SEQ / 64, NHEADS, BATCH), 256, ATTN_SMEM>>>(p_qkv, p_zh, p_zl);

    // 5) O projection + residual -> resid_mid f32
    gemm_mma<2><<<dim3(DMODEL / 128, MTOT / 128), 256, GSMEM>>>(
        p_zh, p_zl, p_woh, p_wol, bO, resid_pre, p_mid, nullptr, nullptr, DMODEL, DMODEL, DMODEL / 64);

    // 6) LN2 -> bf16 hi/lo
    ln_kernel<<<MTOT, 256>>>(p_mid, ln2w, ln2b, p_xn2h, p_xn2l);

    // 7) MLP in + GELU -> hidden bf16 hi/lo
    gemm_mma<1><<<dim3(DMLP / 128, MTOT / 128), 256, GSMEM>>>(
        p_xn2h, p_xn2l, p_wih, p_wil, bin, nullptr, nullptr, p_hidh, p_hidl, DMLP, DMODEL, DMODEL / 64);

    // 8) MLP out + residual -> out f32
    gemm_mma<2><<<dim3(DMODEL / 128, MTOT / 128), 256, GSMEM>>>(
        p_hidh, p_hidl, p_wouth, p_woutl, bout, p_mid, out, nullptr, nullptr, DMODEL, DMLP, DMLP / 64);
}

// round 5
// speedup vs baseline: 5.1380x; 1.4478x over previous
#include <cuda_runtime.h>
#include <cuda_bf16.h>
#include <math.h>
#include <stdint.h>

#define MTOT   8192
#define DMODEL 768
#define NHEADS 12
#define DHEAD  64
#define DMLP   3072
#define SEQ    1024
#define BATCH  8
#define QKVW   (3*DMODEL)

typedef __nv_bfloat16 bf16;

// ---------------- scratch ----------------
__device__ __align__(256) bf16 g_xn_hi [MTOT*DMODEL];
__device__ __align__(256) bf16 g_xn_lo [MTOT*DMODEL];
__device__ __align__(256) bf16 g_xn2_hi[MTOT*DMODEL];
__device__ __align__(256) bf16 g_xn2_lo[MTOT*DMODEL];
__device__ __align__(256) bf16 g_z_hi  [MTOT*DMODEL];
__device__ __align__(256) bf16 g_z_lo  [MTOT*DMODEL];
__device__ __align__(256) bf16 g_hid_hi[(size_t)MTOT*DMLP];
__device__ __align__(256) bf16 g_hid_lo[(size_t)MTOT*DMLP];
__device__ __align__(256) bf16 g_qkv_hi[(size_t)MTOT*QKVW];
__device__ __align__(256) bf16 g_qkv_lo[(size_t)MTOT*QKVW];
__device__ __align__(256) bf16 g_wqkv_hi[QKVW*DMODEL];
__device__ __align__(256) bf16 g_wqkv_lo[QKVW*DMODEL];
__device__ __align__(256) bf16 g_wo_hi [DMODEL*DMODEL];
__device__ __align__(256) bf16 g_wo_lo [DMODEL*DMODEL];
__device__ __align__(256) bf16 g_win_hi[DMODEL*DMLP];
__device__ __align__(256) bf16 g_win_lo[DMODEL*DMLP];
__device__ __align__(256) bf16 g_wout_hi[DMLP*DMODEL];
__device__ __align__(256) bf16 g_wout_lo[DMLP*DMODEL];
__device__ float g_bqkv[QKVW];
__device__ float g_mid [MTOT*DMODEL];

// ---------------- helpers ----------------
__device__ __forceinline__ uint32_t smem_u32(const void* p) {
    uint32_t a;
    asm("{ .reg .u64 t; cvta.to.shared.u64 t, %1; cvt.u32.u64 %0, t; }" : "=r"(a) : "l"(p));
    return a;
}
#define SW128(o) ((o) ^ (((o) >> 3) & 0x70))

__device__ __forceinline__ void cp16(uint32_t dst, const void* src) {
    asm volatile("cp.async.cg.shared.global [%0], [%1], 16;" :: "r"(dst), "l"(src));
}
#define CP_COMMIT() asm volatile("cp.async.commit_group;" ::: "memory")
#define CP_WAIT(n)  asm volatile("cp.async.wait_group %0;" :: "n"(n) : "memory")

#define LDSM4(r0, r1, r2, r3, addr) \
    asm volatile("ldmatrix.sync.aligned.m8n8.x4.shared.b16 {%0,%1,%2,%3},[%4];" \
        : "=r"(r0), "=r"(r1), "=r"(r2), "=r"(r3) : "r"(addr))
#define LDSM4T(r0, r1, r2, r3, addr) \
    asm volatile("ldmatrix.sync.aligned.m8n8.x4.trans.shared.b16 {%0,%1,%2,%3},[%4];" \
        : "=r"(r0), "=r"(r1), "=r"(r2), "=r"(r3) : "r"(addr))

#define MMA16816(d, a, b0, b1) \
    asm volatile("mma.sync.aligned.m16n8k16.row.col.f32.bf16.bf16.f32 " \
        "{%0,%1,%2,%3},{%4,%5,%6,%7},{%8,%9},{%0,%1,%2,%3};" \
        : "+f"((d)[0]), "+f"((d)[1]), "+f"((d)[2]), "+f"((d)[3]) \
        : "r"((a)[0]), "r"((a)[1]), "r"((a)[2]), "r"((a)[3]), "r"(b0), "r"(b1))

__device__ __forceinline__ float gelu_new_f(float x) {
    float x3 = x * x * x;
    return 0.5f * x * (1.0f + tanhf(0.7978845608028654f * (x + 0.044715f * x3)));
}
__device__ __forceinline__ void split_bf16(float x, bf16& h, bf16& l) {
    h = __float2bfloat16(x);
    l = __float2bfloat16(x - __bfloat162float(h));
}
__device__ __forceinline__ uint32_t pack_bf162(bf16 a, bf16 b) {
    __nv_bfloat162 t(a, b);
    return *(uint32_t*)&t;
}
__device__ __forceinline__ uint32_t pack_hi2(float a, float b) {
    return pack_bf162(__float2bfloat16(a), __float2bfloat16(b));
}
__device__ __forceinline__ uint32_t pack_lo2(float a, float b) {
    bf16 ha = __float2bfloat16(a), hb = __float2bfloat16(b);
    return pack_bf162(__float2bfloat16(a - __bfloat162float(ha)),
                      __float2bfloat16(b - __bfloat162float(hb)));
}

// ---------------- tiled batched transpose pack: src[R][C] f32 -> dst[C][R] bf16 hi/lo ----
__global__ __launch_bounds__(256)
void pack_T(const float* __restrict__ src, bf16* __restrict__ dh, bf16* __restrict__ dl,
            int R, int C, long sbs, long dbs, float scale) {
    __shared__ float t[32][33];
    int bz = blockIdx.z;
    const float* s = src + (size_t)bz * sbs;
    bf16* oh = dh + (size_t)bz * dbs;
    bf16* ol = dl + (size_t)bz * dbs;
    int r0 = blockIdx.y * 32, c0 = blockIdx.x * 32;
    int tr = threadIdx.x >> 5, tc = threadIdx.x & 31;
#pragma unroll
    for (int i = 0; i < 4; i++)
        t[tr + i * 8][tc] = s[(size_t)(r0 + tr + i * 8) * C + c0 + tc];
    __syncthreads();
#pragma unroll
    for (int i = 0; i < 4; i++) {
        int cc = tr + i * 8;
        float v = t[tc][cc] * scale;
        bf16 h, l; split_bf16(v, h, l);
        size_t di = (size_t)(c0 + cc) * R + r0 + tc;
        oh[di] = h; ol[di] = l;
    }
}

__global__ void pack_bqkv_kernel(const float* __restrict__ bQ, const float* __restrict__ bK,
                                 const float* __restrict__ bV) {
    int i = threadIdx.x + blockIdx.x * 256;
    if (i >= QKVW) return;
    g_bqkv[i] = (i < DMODEL) ? bQ[i] * 0.125f : (i < 2 * DMODEL ? bK[i - DMODEL] : bV[i - 2 * DMODEL]);
}

// ---------------- layernorm -> bf16 hi/lo ----------------
__global__ __launch_bounds__(256)
void ln_kernel(const float* __restrict__ x, const float* __restrict__ w, const float* __restrict__ b,
               bf16* __restrict__ yh, bf16* __restrict__ yl) {
    __shared__ float ws[8], wq[8], stats[2];
    int row = blockIdx.x, tid = threadIdx.x;
    const float* xr = x + (size_t)row * DMODEL;
    float v0 = xr[tid], v1 = xr[tid + 256], v2 = xr[tid + 512];
    float s = v0 + v1 + v2, sq = v0 * v0 + v1 * v1 + v2 * v2;
#pragma unroll
    for (int o = 16; o > 0; o >>= 1) {
        s  += __shfl_xor_sync(0xffffffffu, s,  o);
        sq += __shfl_xor_sync(0xffffffffu, sq, o);
    }
    if ((tid & 31) == 0) { ws[tid >> 5] = s; wq[tid >> 5] = sq; }
    __syncthreads();
    if (tid == 0) {
        float ts = 0.f, tq = 0.f;
#pragma unroll
        for (int i = 0; i < 8; i++) { ts += ws[i]; tq += wq[i]; }
        float mean = ts * (1.0f / DMODEL);
        float var  = tq * (1.0f / DMODEL) - mean * mean;
        stats[0] = mean; stats[1] = rsqrtf(var + 1e-5f);
    }
    __syncthreads();
    float mean = stats[0], rstd = stats[1];
    size_t base = (size_t)row * DMODEL;
#pragma unroll
    for (int u = 0; u < 3; u++) {
        int c = tid + u * 256;
        float y = ((u == 0 ? v0 : u == 1 ? v1 : v2) - mean) * rstd * w[c] + b[c];
        bf16 hi, lo; split_bf16(y, hi, lo);
        yh[base + c] = hi; yl[base + c] = lo;
    }
}

// ---------------- mma.sync GEMM: C[M,N] = A[M,K] * B[N,K]^T, split-bf16 -----
// EPI: 0 = bias->f32 ; 1 = bias+gelu->bf16 split ; 2 = bias+resid->f32 ; 3 = bias->bf16 split
#define GTILE 16384
#define GSTG  (4*GTILE)
#define GSMEM (1024 + 2*GSTG)

__device__ __forceinline__ void stage_tile(uint32_t sbase, const bf16* src, int K, int tid) {
#pragma unroll
    for (int it = 0; it < 4; it++) {
        int idx = tid + it * 256;
        int row = idx >> 3, seg = idx & 7;
        uint32_t off = (uint32_t)(row * 128 + seg * 16);
        cp16(sbase + SW128(off), src + (size_t)row * K + seg * 8);
    }
}
__device__ __forceinline__ void stage_chunk(uint32_t tb, const bf16* Ah, const bf16* Al,
                                            const bf16* Bh, const bf16* Bl,
                                            int k0, int K, int tid) {
    stage_tile(tb,             Ah + k0, K, tid);
    stage_tile(tb + GTILE,     Al + k0, K, tid);
    stage_tile(tb + 2 * GTILE, Bh + k0, K, tid);
    stage_tile(tb + 3 * GTILE, Bl + k0, K, tid);
    CP_COMMIT();
}

template <int EPI>
__global__ __launch_bounds__(256, 1)
void gemm_mma(const bf16* __restrict__ Ahi, const bf16* __restrict__ Alo,
              const bf16* __restrict__ Bhi, const bf16* __restrict__ Blo,
              const float* __restrict__ bias, const float* __restrict__ R,
              float* __restrict__ C, bf16* __restrict__ Chi, bf16* __restrict__ Clo,
              int N, int K, int NC) {
    extern __shared__ char smraw[];
    uint32_t sb = (smem_u32(smraw) + 1023) & ~1023u;
    int tid = threadIdx.x;
    int row0 = blockIdx.y * 128, col0 = blockIdx.x * 128;
    int wid = tid >> 5, lane = tid & 31;
    int wm = (wid >> 2) * 64, wn = (wid & 3) * 32;

    const bf16* Ah = Ahi + (size_t)row0 * K;
    const bf16* Al = Alo + (size_t)row0 * K;
    const bf16* Bh = Bhi + (size_t)col0 * K;
    const bf16* Bl = Blo + (size_t)col0 * K;

    stage_chunk(sb,        Ah, Al, Bh, Bl, 0,  K, tid);
    stage_chunk(sb + GSTG, Ah, Al, Bh, Bl, 64, K, tid);

    float acc[4][4][4];
#pragma unroll
    for (int mi = 0; mi < 4; mi++)
#pragma unroll
        for (int ni = 0; ni < 4; ni++)
#pragma unroll
            for (int q = 0; q < 4; q++) acc[mi][ni][q] = 0.f;

    int ar = lane & 15, ahalf = lane >> 4;
    int brow = (lane & 7) + ((lane >> 4) << 3);
    int bhalf = (lane >> 3) & 1;

    for (int i = 0; i < NC; i++) {
        if (i < NC - 1) CP_WAIT(1); else CP_WAIT(0);
        __syncthreads();
        uint32_t tb = sb + (uint32_t)(i & 1) * GSTG;
#pragma unroll
        for (int ks = 0; ks < 4; ks++) {
            uint32_t ahr[4][4], alr[4][4], bhr[2][4], blr[2][4];
#pragma unroll
            for (int mi = 0; mi < 4; mi++) {
                uint32_t off = (uint32_t)((wm + mi * 16 + ar) * 128 + ks * 32 + ahalf * 16);
                uint32_t sw = SW128(off);
                LDSM4(ahr[mi][0], ahr[mi][1], ahr[mi][2], ahr[mi][3], tb + sw);
                LDSM4(alr[mi][0], alr[mi][1], alr[mi][2], alr[mi][3], tb + GTILE + sw);
            }
#pragma unroll
            for (int nb = 0; nb < 2; nb++) {
                uint32_t off = (uint32_t)((wn + nb * 16 + brow) * 128 + ks * 32 + bhalf * 16);
                uint32_t sw = SW128(off);
                LDSM4(bhr[nb][0], bhr[nb][1], bhr[nb][2], bhr[nb][3], tb + 2 * GTILE + sw);
                LDSM4(blr[nb][0], blr[nb][1], blr[nb][2], blr[nb][3], tb + 3 * GTILE + sw);
            }
#pragma unroll
            for (int mi = 0; mi < 4; mi++)
#pragma unroll
                for (int ni = 0; ni < 4; ni++) {
                    int nb = ni >> 1, p = (ni & 1) * 2;
                    MMA16816(acc[mi][ni], ahr[mi], bhr[nb][p], bhr[nb][p + 1]);
                    MMA16816(acc[mi][ni], ahr[mi], blr[nb][p], blr[nb][p + 1]);
                    MMA16816(acc[mi][ni], alr[mi], bhr[nb][p], bhr[nb][p + 1]);
                }
        }
        __syncthreads();
        if (i + 2 < NC)
            stage_chunk(sb + (uint32_t)(i & 1) * GSTG, Ah, Al, Bh, Bl, (i + 2) * 64, K, tid);
    }

#pragma unroll
    for (int mi = 0; mi < 4; mi++) {
#pragma unroll
        for (int ni = 0; ni < 4; ni++) {
            int r = row0 + wm + mi * 16 + (lane >> 2);
            int c = col0 + wn + ni * 8 + (lane & 3) * 2;
            float b0 = bias[c], b1 = bias[c + 1];
#pragma unroll
            for (int half = 0; half < 2; half++) {
                int rr = r + half * 8;
                float v0 = acc[mi][ni][2 * half]     + b0;
                float v1 = acc[mi][ni][2 * half + 1] + b1;
                if (EPI == 1 || EPI == 3) {
                    if (EPI == 1) { v0 = gelu_new_f(v0); v1 = gelu_new_f(v1); }
                    *(uint32_t*)&Chi[(size_t)rr * N + c] = pack_hi2(v0, v1);
                    *(uint32_t*)&Clo[(size_t)rr * N + c] = pack_lo2(v0, v1);
                } else {
                    if (EPI == 2) {
                        float2 rv = *(const float2*)&R[(size_t)rr * N + c];
                        v0 += rv.x; v1 += rv.y;
                    }
                    *(float2*)&C[(size_t)rr * N + c] = make_float2(v0, v1);
                }
            }
        }
    }
}

// ---------------- mma flash attention, split-bf16 ----------------
// Q tile 128 rows, KV tile 64, 8 warps (16 q-rows each), double-buffered KV.
// smem: Qh 16K | Ql 16K | 2 stages x (Kh 8K, Kl 8K, Vh 8K, Vl 8K)
#define ASTG0 32768
#define ASTG  32768
#define ASMEM (1024 + ASTG0 + 2*ASTG)
#define NEGINF (-1e30f)

__device__ __forceinline__ void attn_stage_kv(uint32_t kb, const bf16* kh, const bf16* kl,
                                              const bf16* vh, const bf16* vl, int tid) {
#pragma unroll
    for (int it = 0; it < 2; it++) {
        int idx = tid + it * 256;
        int row = idx >> 3, seg = idx & 7;
        uint32_t off = SW128((uint32_t)(row * 128 + seg * 16));
        size_t g = (size_t)row * QKVW + seg * 8;
        cp16(kb + off,         kh + g);
        cp16(kb + 8192 + off,  kl + g);
        cp16(kb + 16384 + off, vh + g);
        cp16(kb + 24576 + off, vl + g);
    }
}

__global__ __launch_bounds__(256, 2)
void attn_mma(const bf16* __restrict__ qkvh, const bf16* __restrict__ qkvl,
              bf16* __restrict__ zh, bf16* __restrict__ zl) {
    extern __shared__ char smraw[];
    uint32_t sq = (smem_u32(smraw) + 1023) & ~1023u;
    uint32_t sstage = sq + ASTG0;
    int tid = threadIdx.x, wid = tid >> 5, lane = tid & 31;
    int qt = blockIdx.x, h = blockIdx.y, b = blockIdx.z;
    int q0 = qt * 128;
    size_t tokbase = (size_t)b * SEQ * QKVW;
    const bf16* qhp = qkvh + tokbase + (size_t)q0 * QKVW + h * DHEAD;
    const bf16* qlp = qkvl + tokbase + (size_t)q0 * QKVW + h * DHEAD;
    const bf16* khp = qkvh + tokbase + DMODEL + h * DHEAD;
    const bf16* klp = qkvl + tokbase + DMODEL + h * DHEAD;
    const bf16* vhp = qkvh + tokbase + 2 * DMODEL + h * DHEAD;
    const bf16* vlp = qkvl + tokbase + 2 * DMODEL + h * DHEAD;

    // stage Q (128 rows x 64 cols bf16, hi+lo)
#pragma unroll
    for (int it = 0; it < 4; it++) {
        int idx = tid + it * 256;
        int row = idx >> 3, seg = idx & 7;
        uint32_t off = SW128((uint32_t)(row * 128 + seg * 16));
        size_t g = (size_t)row * QKVW + seg * 8;
        cp16(sq + off,         qhp + g);
        cp16(sq + 16384 + off, qlp + g);
    }
    CP_COMMIT();
    attn_stage_kv(sstage, khp, klp, vhp, vlp, tid);
    CP_COMMIT();

    float o[8][4];
#pragma unroll
    for (int d = 0; d < 8; d++)
#pragma unroll
        for (int q = 0; q < 4; q++) o[d][q] = 0.f;
    float m0 = NEGINF, m1 = NEGINF, l0 = 0.f, l1 = 0.f;

    int ar = lane & 15, ahalf = lane >> 4;
    int brow = (lane & 7) + ((lane >> 4) << 3);
    int bhalf = (lane >> 3) & 1;
    int vkrow = (lane & 7) + (((lane >> 3) & 1) << 3);
    int vncol = (lane >> 4) * 8;
    int r0g = q0 + wid * 16 + (lane >> 2);

    int nkt = 2 * qt + 2;
    for (int kt = 0; kt < nkt; kt++) {
        __syncthreads();
        if (kt + 1 < nkt) {
            attn_stage_kv(sstage + (uint32_t)((kt + 1) & 1) * ASTG,
                          khp + (size_t)(kt + 1) * 64 * QKVW, klp + (size_t)(kt + 1) * 64 * QKVW,
                          vhp + (size_t)(kt + 1) * 64 * QKVW, vlp + (size_t)(kt + 1) * 64 * QKVW, tid);
            CP_COMMIT();
            CP_WAIT(1);
        } else {
            CP_WAIT(0);
        }
        __syncthreads();
        uint32_t kb = sstage + (uint32_t)(kt & 1) * ASTG;

        // S = Q K^T  (16 x 64 per warp)
        float s[8][4];
#pragma unroll
        for (int ni = 0; ni < 8; ni++)
#pragma unroll
            for (int q = 0; q < 4; q++) s[ni][q] = 0.f;
#pragma unroll
        for (int ks = 0; ks < 4; ks++) {
            uint32_t ah[4], al[4];
            uint32_t offa = SW128((uint32_t)((wid * 16 + ar) * 128 + ks * 32 + ahalf * 16));
            LDSM4(ah[0], ah[1], ah[2], ah[3], sq + offa);
            LDSM4(al[0], al[1], al[2], al[3], sq + 16384 + offa);
#pragma unroll
            for (int nb = 0; nb < 4; nb++) {
                uint32_t bh[4], bl[4];
                uint32_t offb = SW128((uint32_t)((nb * 16 + brow) * 128 + ks * 32 + bhalf * 16));
                LDSM4(bh[0], bh[1], bh[2], bh[3], kb + offb);
                LDSM4(bl[0], bl[1], bl[2], bl[3], kb + 8192 + offb);
#pragma unroll
                for (int niL = 0; niL < 2; niL++) {
                    int ni = nb * 2 + niL, p = niL * 2;
                    MMA16816(s[ni], ah, bh[p], bh[p + 1]);
                    MMA16816(s[ni], ah, bl[p], bl[p + 1]);
                    MMA16816(s[ni], al, bh[p], bh[p + 1]);
                }
            }
        }

        // causal mask (only last two kv tiles can clip)
        if (kt >= 2 * qt) {
            int cbase = kt * 64 + (lane & 3) * 2;
#pragma unroll
            for (int ni = 0; ni < 8; ni++) {
                int c0 = cbase + ni * 8, c1 = c0 + 1;
                if (c0 > r0g)     s[ni][0] = NEGINF;
                if (c1 > r0g)     s[ni][1] = NEGINF;
                if (c0 > r0g + 8) s[ni][2] = NEGINF;
                if (c1 > r0g + 8) s[ni][3] = NEGINF;
            }
        }

        // online softmax
        float tm0 = NEGINF, tm1 = NEGINF;
#pragma unroll
        for (int ni = 0; ni < 8; ni++) {
            tm0 = fmaxf(tm0, fmaxf(s[ni][0], s[ni][1]));
            tm1 = fmaxf(tm1, fmaxf(s[ni][2], s[ni][3]));
        }
        tm0 = fmaxf(tm0, __shfl_xor_sync(0xffffffffu, tm0, 1));
        tm0 = fmaxf(tm0, __shfl_xor_sync(0xffffffffu, tm0, 2));
        tm1 = fmaxf(tm1, __shfl_xor_sync(0xffffffffu, tm1, 1));
        tm1 = fmaxf(tm1, __shfl_xor_sync(0xffffffffu, tm1, 2));
        float nm0 = fmaxf(m0, tm0), nm1 = fmaxf(m1, tm1);
        float alpha0 = __expf(m0 - nm0), alpha1 = __expf(m1 - nm1);
        m0 = nm0; m1 = nm1;
        float rs0 = 0.f, rs1 = 0.f;
#pragma unroll
        for (int ni = 0; ni < 8; ni++) {
            s[ni][0] = __expf(s[ni][0] - nm0);
            s[ni][1] = __expf(s[ni][1] - nm0);
            s[ni][2] = __expf(s[ni][2] - nm1);
            s[ni][3] = __expf(s[ni][3] - nm1);
            rs0 += s[ni][0] + s[ni][1];
            rs1 += s[ni][2] + s[ni][3];
        }
        rs0 += __shfl_xor_sync(0xffffffffu, rs0, 1);
        rs0 += __shfl_xor_sync(0xffffffffu, rs0, 2);
        rs1 += __shfl_xor_sync(0xffffffffu, rs1, 1);
        rs1 += __shfl_xor_sync(0xffffffffu, rs1, 2);
        l0 = l0 * alpha0 + rs0;
        l1 = l1 * alpha1 + rs1;
#pragma unroll
        for (int d = 0; d < 8; d++) {
            o[d][0] *= alpha0; o[d][1] *= alpha0;
            o[d][2] *= alpha1; o[d][3] *= alpha1;
        }

        // O += P V  (P split hi/lo, V split hi/lo from smem via ldmatrix.trans)
#pragma unroll
        for (int ks = 0; ks < 4; ks++) {
            uint32_t pa_h[4], pa_l[4];
            pa_h[0] = pack_hi2(s[2 * ks][0], s[2 * ks][1]);
            pa_h[1] = pack_hi2(s[2 * ks][2], s[2 * ks][3]);
            pa_h[2] = pack_hi2(s[2 * ks + 1][0], s[2 * ks + 1][1]);
            pa_h[3] = pack_hi2(s[2 * ks + 1][2], s[2 * ks + 1][3]);
            pa_l[0] = pack_lo2(s[2 * ks][0], s[2 * ks][1]);
            pa_l[1] = pack_lo2(s[2 * ks][2], s[2 * ks][3]);
            pa_l[2] = pack_lo2(s[2 * ks + 1][0], s[2 * ks + 1][1]);
            pa_l[3] = pack_lo2(s[2 * ks + 1][2], s[2 * ks + 1][3]);
#pragma unroll
            for (int nb = 0; nb < 4; nb++) {
                uint32_t vh[4], vl[4];
                uint32_t offv = SW128((uint32_t)((ks * 16 + vkrow) * 128 + nb * 32 + vncol * 2));
                LDSM4T(vh[0], vh[1], vh[2], vh[3], kb + 16384 + offv);
                LDSM4T(vl[0], vl[1], vl[2], vl[3], kb + 24576 + offv);
#pragma unroll
                for (int niL = 0; niL < 2; niL++) {
                    int d = nb * 2 + niL, p = niL * 2;
                    MMA16816(o[d], pa_h, vh[p], vh[p + 1]);
                    MMA16816(o[d], pa_h, vl[p], vl[p + 1]);
                    MMA16816(o[d], pa_l, vh[p], vh[p + 1]);
                }
            }
        }
    }

    // epilogue: normalize and write z as bf16 hi/lo
    float inv0 = 1.0f / l0, inv1 = 1.0f / l1;
    size_t rb0 = ((size_t)b * SEQ + q0 + wid * 16 + (lane >> 2)) * DMODEL + h * DHEAD + (lane & 3) * 2;
    size_t rb1 = rb0 + 8 * DMODEL;
#pragma unroll
    for (int d = 0; d < 8; d++) {
        float a0 = o[d][0] * inv0, a1 = o[d][1] * inv0;
        float b0 = o[d][2] * inv1, b1 = o[d][3] * inv1;
        *(uint32_t*)&zh[rb0 + d * 8] = pack_hi2(a0, a1);
        *(uint32_t*)&zl[rb0 + d * 8] = pack_lo2(a0, a1);
        *(uint32_t*)&zh[rb1 + d * 8] = pack_hi2(b0, b1);
        *(uint32_t*)&zl[rb1 + d * 8] = pack_lo2(b0, b1);
    }
}

// ---------------- launch ----------------
extern "C" void kernel_launch(void* const* d_in, const int* in_sizes, int n_in,
                              void* d_out, int out_size) {
    const float* resid_pre = (const float*)d_in[0];
    const float* WQ  = (const float*)d_in[1];
    const float* WK  = (const float*)d_in[2];
    const float* WV  = (const float*)d_in[3];
    const float* WO  = (const float*)d_in[4];
    const float* bQ  = (const float*)d_in[5];
    const float* bK  = (const float*)d_in[6];
    const float* bV  = (const float*)d_in[7];
    const float* bO  = (const float*)d_in[8];
    const float* ln1w = (const float*)d_in[9];
    const float* ln1b = (const float*)d_in[10];
    const float* ln2w = (const float*)d_in[11];
    const float* ln2b = (const float*)d_in[12];
    const float* Win  = (const float*)d_in[13];
    const float* bin  = (const float*)d_in[14];
    const float* Wout = (const float*)d_in[15];
    const float* bout = (const float*)d_in[16];
    float* out = (float*)d_out;

    bf16 *p_xnh, *p_xnl, *p_xn2h, *p_xn2l, *p_zh, *p_zl, *p_hidh, *p_hidl, *p_qkvh, *p_qkvl;
    bf16 *p_wqh, *p_wql, *p_woh, *p_wol, *p_wih, *p_wil, *p_wouth, *p_woutl;
    float *p_bqkv, *p_mid;
    cudaGetSymbolAddress((void**)&p_xnh, g_xn_hi);   cudaGetSymbolAddress((void**)&p_xnl, g_xn_lo);
    cudaGetSymbolAddress((void**)&p_xn2h, g_xn2_hi); cudaGetSymbolAddress((void**)&p_xn2l, g_xn2_lo);
    cudaGetSymbolAddress((void**)&p_zh, g_z_hi);     cudaGetSymbolAddress((void**)&p_zl, g_z_lo);
    cudaGetSymbolAddress((void**)&p_hidh, g_hid_hi); cudaGetSymbolAddress((void**)&p_hidl, g_hid_lo);
    cudaGetSymbolAddress((void**)&p_qkvh, g_qkv_hi); cudaGetSymbolAddress((void**)&p_qkvl, g_qkv_lo);
    cudaGetSymbolAddress((void**)&p_wqh, g_wqkv_hi); cudaGetSymbolAddress((void**)&p_wql, g_wqkv_lo);
    cudaGetSymbolAddress((void**)&p_woh, g_wo_hi);   cudaGetSymbolAddress((void**)&p_wol, g_wo_lo);
    cudaGetSymbolAddress((void**)&p_wih, g_win_hi);  cudaGetSymbolAddress((void**)&p_wil, g_win_lo);
    cudaGetSymbolAddress((void**)&p_wouth, g_wout_hi); cudaGetSymbolAddress((void**)&p_woutl, g_wout_lo);
    cudaGetSymbolAddress((void**)&p_bqkv, g_bqkv);
    cudaGetSymbolAddress((void**)&p_mid, g_mid);

    cudaFuncSetAttribute(attn_mma, cudaFuncAttributeMaxDynamicSharedMemorySize, ASMEM);
    cudaFuncSetAttribute(gemm_mma<1>, cudaFuncAttributeMaxDynamicSharedMemorySize, GSMEM);
    cudaFuncSetAttribute(gemm_mma<2>, cudaFuncAttributeMaxDynamicSharedMemorySize, GSMEM);
    cudaFuncSetAttribute(gemm_mma<3>, cudaFuncAttributeMaxDynamicSharedMemorySize, GSMEM);

    // 1) weight packs (tiled transposes; W_Q scaled by 1/8)
    pack_T<<<dim3(2, 24, 12), 256>>>(WQ, p_wqh, p_wql, DMODEL, DHEAD,
                                     (long)DMODEL * DHEAD, (long)DHEAD * DMODEL, 0.125f);
    pack_T<<<dim3(2, 24, 12), 256>>>(WK, p_wqh + DMODEL * DMODEL, p_wql + DMODEL * DMODEL,
                                     DMODEL, DHEAD, (long)DMODEL * DHEAD, (long)DHEAD * DMODEL, 1.0f);
    pack_T<<<dim3(2, 24, 12), 256>>>(WV, p_wqh + 2 * DMODEL * DMODEL, p_wql + 2 * DMODEL * DMODEL,
                                     DMODEL, DHEAD, (long)DMODEL * DHEAD, (long)DHEAD * DMODEL, 1.0f);
    pack_T<<<dim3(24, 24, 1), 256>>>(WO, p_woh, p_wol, DMODEL, DMODEL, 0, 0, 1.0f);
    pack_T<<<dim3(96, 24, 1), 256>>>(Win, p_wih, p_wil, DMODEL, DMLP, 0, 0, 1.0f);
    pack_T<<<dim3(24, 96, 1), 256>>>(Wout, p_wouth, p_woutl, DMLP, DMODEL, 0, 0, 1.0f);
    pack_bqkv_kernel<<<(QKVW + 255) / 256, 256>>>(bQ, bK, bV);

    // 2) LN1 -> bf16 hi/lo
    ln_kernel<<<MTOT, 256>>>(resid_pre, ln1w, ln1b, p_xnh, p_xnl);

    // 3) QKV projection -> bf16 hi/lo (Q pre-scaled via weights)
    gemm_mma<3><<<dim3(QKVW / 128, MTOT / 128), 256, GSMEM>>>(
        p_xnh, p_xnl, p_wqh, p_wql, p_bqkv, nullptr, nullptr, p_qkvh, p_qkvl, QKVW, DMODEL, DMODEL / 64);

    // 4) causal flash attention (tensor cores) -> z bf16 hi/lo
    attn_mma<<<dim3(SEQ / 128, NHEADS, BATCH), 256, ASMEM>>>(p_qkvh, p_qkvl, p_zh, p_zl);

    // 5) O projection + residual -> resid_mid f32
    gemm_mma<2><<<dim3(DMODEL / 128, MTOT / 128), 256, GSMEM>>>(
        p_zh, p_zl, p_woh, p_wol, bO, resid_pre, p_mid, nullptr, nullptr, DMODEL, DMODEL, DMODEL / 64);

    // 6) LN2 -> bf16 hi/lo
    ln_kernel<<<MTOT, 256>>>(p_mid, ln2w, ln2b, p_xn2h, p_xn2l);

    // 7) MLP in + GELU -> hidden bf16 hi/lo
    gemm_mma<1><<<dim3(DMLP / 128, MTOT / 128), 256, GSMEM>>>(
        p_xn2h, p_xn2l, p_wih, p_wil, bin, nullptr, nullptr, p_hidh, p_hidl, DMLP, DMODEL, DMODEL / 64);

    // 8) MLP out + residual -> out f32
    gemm_mma<2><<<dim3(DMODEL / 128, MTOT / 128), 256, GSMEM>>>(
        p_hidh, p_hidl, p_wouth, p_woutl, bout, p_mid, out, nullptr, nullptr, DMODEL, DMLP, DMLP / 64);
}

// round 8
// speedup vs baseline: 6.3121x; 1.2285x over previous
#include <cuda_runtime.h>
#include <cuda_bf16.h>
#include <math.h>
#include <stdint.h>

#define MTOT   8192
#define DMODEL 768
#define NHEADS 12
#define DHEAD  64
#define DMLP   3072
#define SEQ    1024
#define BATCH  8
#define QKVW   (3*DMODEL)

typedef __nv_bfloat16 bf16;

// ---------------- scratch ----------------
__device__ __align__(256) float g_xn [MTOT*DMODEL];
__device__ __align__(256) float g_xn2[MTOT*DMODEL];
__device__ __align__(256) float g_z  [MTOT*DMODEL];
__device__ __align__(256) float g_hid[(size_t)MTOT*DMLP];
__device__ __align__(256) bf16 g_qkv_hi[(size_t)MTOT*QKVW];
__device__ __align__(256) bf16 g_qkv_lo[(size_t)MTOT*QKVW];
__device__ __align__(256) float g_wqkv[QKVW*DMODEL];
__device__ __align__(256) float g_wo  [DMODEL*DMODEL];
__device__ __align__(256) float g_win [DMODEL*DMLP];
__device__ __align__(256) float g_wout[DMLP*DMODEL];
__device__ float g_bqkv[QKVW];
__device__ float g_mid [MTOT*DMODEL];

// ---------------- helpers ----------------
__device__ __forceinline__ uint32_t smem_u32(const void* p) {
    uint32_t a;
    asm("{ .reg .u64 t; cvta.to.shared.u64 t, %1; cvt.u32.u64 %0, t; }" : "=r"(a) : "l"(p));
    return a;
}
#define SW128(o) ((o) ^ (((o) >> 3) & 0x70))

__device__ __forceinline__ void cp16(uint32_t dst, const void* src) {
    asm volatile("cp.async.cg.shared.global [%0], [%1], 16;" :: "r"(dst), "l"(src));
}
#define CP_COMMIT() asm volatile("cp.async.commit_group;" ::: "memory")
#define CP_WAIT(n)  asm volatile("cp.async.wait_group %0;" :: "n"(n) : "memory")

#define LDSM4(r0, r1, r2, r3, addr) \
    asm volatile("ldmatrix.sync.aligned.m8n8.x4.shared.b16 {%0,%1,%2,%3},[%4];" \
        : "=r"(r0), "=r"(r1), "=r"(r2), "=r"(r3) : "r"(addr))
#define LDSM4T(r0, r1, r2, r3, addr) \
    asm volatile("ldmatrix.sync.aligned.m8n8.x4.trans.shared.b16 {%0,%1,%2,%3},[%4];" \
        : "=r"(r0), "=r"(r1), "=r"(r2), "=r"(r3) : "r"(addr))

#define MMA16816(d, a, b0, b1) \
    asm volatile("mma.sync.aligned.m16n8k16.row.col.f32.bf16.bf16.f32 " \
        "{%0,%1,%2,%3},{%4,%5,%6,%7},{%8,%9},{%0,%1,%2,%3};" \
        : "+f"((d)[0]), "+f"((d)[1]), "+f"((d)[2]), "+f"((d)[3]) \
        : "r"((a)[0]), "r"((a)[1]), "r"((a)[2]), "r"((a)[3]), "r"(b0), "r"(b1))

#define MMATF32(d, a, b0, b1) \
    asm volatile("mma.sync.aligned.m16n8k8.row.col.f32.tf32.tf32.f32 " \
        "{%0,%1,%2,%3},{%4,%5,%6,%7},{%8,%9},{%0,%1,%2,%3};" \
        : "+f"((d)[0]), "+f"((d)[1]), "+f"((d)[2]), "+f"((d)[3]) \
        : "r"((a)[0]), "r"((a)[1]), "r"((a)[2]), "r"((a)[3]), "r"(b0), "r"(b1))

__device__ __forceinline__ float to_tf32(float x) {
    uint32_t u;
    asm("cvt.rna.tf32.f32 %0, %1;" : "=r"(u) : "f"(x));
    return __uint_as_float(u);
}
__device__ __forceinline__ float gelu_new_f(float x) {
    float x3 = x * x * x;
    return 0.5f * x * (1.0f + tanhf(0.7978845608028654f * (x + 0.044715f * x3)));
}
__device__ __forceinline__ void split_bf16(float x, bf16& h, bf16& l) {
    h = __float2bfloat16(x);
    l = __float2bfloat16(x - __bfloat162float(h));
}
__device__ __forceinline__ uint32_t pack_bf162(bf16 a, bf16 b) {
    __nv_bfloat162 t(a, b);
    return *(uint32_t*)&t;
}
__device__ __forceinline__ uint32_t pack_hi2(float a, float b) {
    return pack_bf162(__float2bfloat16(a), __float2bfloat16(b));
}
__device__ __forceinline__ uint32_t pack_lo2(float a, float b) {
    bf16 ha = __float2bfloat16(a), hb = __float2bfloat16(b);
    return pack_bf162(__float2bfloat16(a - __bfloat162float(ha)),
                      __float2bfloat16(b - __bfloat162float(hb)));
}

// ---------------- tiled transpose pack: src[R][C] f32 -> dst[C][R] tf32-rounded f32 ----
__global__ __launch_bounds__(256)
void pack_T(const float* __restrict__ src, float* __restrict__ dst,
            int R, int C, long sbs, long dbs, float scale) {
    __shared__ float t[32][33];
    int bz = blockIdx.z;
    const float* s = src + (size_t)bz * sbs;
    float* o = dst + (size_t)bz * dbs;
    int r0 = blockIdx.y * 32, c0 = blockIdx.x * 32;
    int tr = threadIdx.x >> 5, tc = threadIdx.x & 31;
#pragma unroll
    for (int i = 0; i < 4; i++)
        t[tr + i * 8][tc] = s[(size_t)(r0 + tr + i * 8) * C + c0 + tc];
    __syncthreads();
#pragma unroll
    for (int i = 0; i < 4; i++) {
        int cc = tr + i * 8;
        o[(size_t)(c0 + cc) * R + r0 + tc] = to_tf32(t[tc][cc] * scale);
    }
}

__global__ void pack_bqkv_kernel(const float* __restrict__ bQ, const float* __restrict__ bK,
                                 const float* __restrict__ bV) {
    int i = threadIdx.x + blockIdx.x * 256;
    if (i >= QKVW) return;
    g_bqkv[i] = (i < DMODEL) ? bQ[i] * 0.125f : (i < 2 * DMODEL ? bK[i - DMODEL] : bV[i - 2 * DMODEL]);
}

// ---------------- layernorm -> tf32-rounded f32 ----------------
__global__ __launch_bounds__(256)
void ln_kernel(const float* __restrict__ x, const float* __restrict__ w, const float* __restrict__ b,
               float* __restrict__ y) {
    __shared__ float ws[8], wq[8], stats[2];
    int row = blockIdx.x, tid = threadIdx.x;
    const float* xr = x + (size_t)row * DMODEL;
    float v0 = xr[tid], v1 = xr[tid + 256], v2 = xr[tid + 512];
    float s = v0 + v1 + v2, sq = v0 * v0 + v1 * v1 + v2 * v2;
#pragma unroll
    for (int o = 16; o > 0; o >>= 1) {
        s  += __shfl_xor_sync(0xffffffffu, s,  o);
        sq += __shfl_xor_sync(0xffffffffu, sq, o);
    }
    if ((tid & 31) == 0) { ws[tid >> 5] = s; wq[tid >> 5] = sq; }
    __syncthreads();
    if (tid == 0) {
        float ts = 0.f, tq = 0.f;
#pragma unroll
        for (int i = 0; i < 8; i++) { ts += ws[i]; tq += wq[i]; }
        float mean = ts * (1.0f / DMODEL);
        float var  = tq * (1.0f / DMODEL) - mean * mean;
        stats[0] = mean; stats[1] = rsqrtf(var + 1e-5f);
    }
    __syncthreads();
    float mean = stats[0], rstd = stats[1];
    size_t base = (size_t)row * DMODEL;
#pragma unroll
    for (int u = 0; u < 3; u++) {
        int c = tid + u * 256;
        float yv = ((u == 0 ? v0 : u == 1 ? v1 : v2) - mean) * rstd * w[c] + b[c];
        y[base + c] = to_tf32(yv);
    }
}

// ---------------- TF32 GEMM: C[M,N] = A[M,K] * B[N,K]^T ----------------
// 128x128 CTA tile, KC=32, 3-stage cp.async, 8 warps (2x4), 64x32 warp tile.
// EPI: 1 = bias+gelu->tf32 f32 ; 2 = bias+resid->f32 ; 3 = bias->bf16 hi/lo
#define TTILE 16384
#define TSTG  (2*TTILE)
#define TSMEM (1024 + 3*TSTG)

__device__ __forceinline__ void stage_tf(uint32_t tb, const float* A, const float* B,
                                         int k0, int K, int tid) {
#pragma unroll
    for (int it = 0; it < 4; it++) {
        int idx = tid + it * 256;
        int row = idx >> 3, seg = idx & 7;
        uint32_t off = SW128((uint32_t)(row * 128 + seg * 16));
        cp16(tb + off,         A + (size_t)row * K + k0 + seg * 4);
        cp16(tb + TTILE + off, B + (size_t)row * K + k0 + seg * 4);
    }
    CP_COMMIT();
}

template <int EPI>
__global__ __launch_bounds__(256, 2)
void gemm_tf32(const float* __restrict__ A, const float* __restrict__ B,
               const float* __restrict__ bias, const float* __restrict__ R,
               float* __restrict__ C, bf16* __restrict__ Chi, bf16* __restrict__ Clo,
               int N, int K, int NC) {
    extern __shared__ char smraw[];
    uint32_t sb = (smem_u32(smraw) + 1023) & ~1023u;
    int tid = threadIdx.x;
    int row0 = blockIdx.y * 128, col0 = blockIdx.x * 128;
    int wid = tid >> 5, lane = tid & 31;
    int wm = (wid >> 2) * 64, wn = (wid & 3) * 32;

    const float* Ab = A + (size_t)row0 * K;
    const float* Bb = B + (size_t)col0 * K;

    stage_tf(sb,        Ab, Bb, 0,  K, tid);
    stage_tf(sb + TSTG, Ab, Bb, 32, K, tid);

    float acc[4][4][4];
#pragma unroll
    for (int mi = 0; mi < 4; mi++)
#pragma unroll
        for (int ni = 0; ni < 4; ni++)
#pragma unroll
            for (int q = 0; q < 4; q++) acc[mi][ni][q] = 0.f;

    // tf32 ldmatrix lane addressing
    int ar = lane & 15, acol = (lane >> 4) * 16;                 // A fragment
    int brt = (lane & 7) + ((lane >> 4) & 1) * 8;                // B row (n)
    int bct = ((lane >> 3) & 1) * 16;                            // B col bytes (k half)

    for (int i = 0; i < NC; i++) {
        if (i + 2 < NC) {
            stage_tf(sb + (uint32_t)((i + 2) % 3) * TSTG, Ab, Bb, (i + 2) * 32, K, tid);
            CP_WAIT(2);
        } else {
            CP_WAIT(0);
        }
        __syncthreads();
        uint32_t tb = sb + (uint32_t)(i % 3) * TSTG;
#pragma unroll
        for (int ks = 0; ks < 4; ks++) {
            uint32_t af[4][4], bfr[2][4];
#pragma unroll
            for (int mi = 0; mi < 4; mi++) {
                uint32_t off = SW128((uint32_t)((wm + mi * 16 + ar) * 128 + ks * 32 + acol));
                LDSM4(af[mi][0], af[mi][1], af[mi][2], af[mi][3], tb + off);
            }
#pragma unroll
            for (int nb = 0; nb < 2; nb++) {
                uint32_t off = SW128((uint32_t)((wn + nb * 16 + brt) * 128 + ks * 32 + bct));
                LDSM4(bfr[nb][0], bfr[nb][1], bfr[nb][2], bfr[nb][3], tb + TTILE + off);
            }
#pragma unroll
            for (int mi = 0; mi < 4; mi++)
#pragma unroll
                for (int ni = 0; ni < 4; ni++) {
                    int nb = ni >> 1, p = (ni & 1) * 2;
                    MMATF32(acc[mi][ni], af[mi], bfr[nb][p], bfr[nb][p + 1]);
                }
        }
        __syncthreads();
    }

#pragma unroll
    for (int mi = 0; mi < 4; mi++) {
#pragma unroll
        for (int ni = 0; ni < 4; ni++) {
            int r = row0 + wm + mi * 16 + (lane >> 2);
            int c = col0 + wn + ni * 8 + (lane & 3) * 2;
            float b0 = bias[c], b1 = bias[c + 1];
#pragma unroll
            for (int half = 0; half < 2; half++) {
                int rr = r + half * 8;
                float v0 = acc[mi][ni][2 * half]     + b0;
                float v1 = acc[mi][ni][2 * half + 1] + b1;
                if (EPI == 1) {
                    *(float2*)&C[(size_t)rr * N + c] =
                        make_float2(to_tf32(gelu_new_f(v0)), to_tf32(gelu_new_f(v1)));
                } else if (EPI == 3) {
                    *(uint32_t*)&Chi[(size_t)rr * N + c] = pack_hi2(v0, v1);
                    *(uint32_t*)&Clo[(size_t)rr * N + c] = pack_lo2(v0, v1);
                } else {
                    float2 rv = *(const float2*)&R[(size_t)rr * N + c];
                    *(float2*)&C[(size_t)rr * N + c] = make_float2(v0 + rv.x, v1 + rv.y);
                }
            }
        }
    }
}

// ---------------- mma flash attention, split-bf16 (unchanged core) ----------------
#define ASTG0 32768
#define ASTG  32768
#define ASMEM (1024 + ASTG0 + 2*ASTG)
#define NEGINF (-1e30f)

__device__ __forceinline__ void attn_stage_kv(uint32_t kb, const bf16* kh, const bf16* kl,
                                              const bf16* vh, const bf16* vl, int tid) {
#pragma unroll
    for (int it = 0; it < 2; it++) {
        int idx = tid + it * 256;
        int row = idx >> 3, seg = idx & 7;
        uint32_t off = SW128((uint32_t)(row * 128 + seg * 16));
        size_t g = (size_t)row * QKVW + seg * 8;
        cp16(kb + off,         kh + g);
        cp16(kb + 8192 + off,  kl + g);
        cp16(kb + 16384 + off, vh + g);
        cp16(kb + 24576 + off, vl + g);
    }
}

__global__ __launch_bounds__(256, 2)
void attn_mma(const bf16* __restrict__ qkvh, const bf16* __restrict__ qkvl,
              float* __restrict__ z) {
    extern __shared__ char smraw[];
    uint32_t sq = (smem_u32(smraw) + 1023) & ~1023u;
    uint32_t sstage = sq + ASTG0;
    int tid = threadIdx.x, wid = tid >> 5, lane = tid & 31;
    int qt = blockIdx.x, h = blockIdx.y, b = blockIdx.z;
    int q0 = qt * 128;
    size_t tokbase = (size_t)b * SEQ * QKVW;
    const bf16* qhp = qkvh + tokbase + (size_t)q0 * QKVW + h * DHEAD;
    const bf16* qlp = qkvl + tokbase + (size_t)q0 * QKVW + h * DHEAD;
    const bf16* khp = qkvh + tokbase + DMODEL + h * DHEAD;
    const bf16* klp = qkvl + tokbase + DMODEL + h * DHEAD;
    const bf16* vhp = qkvh + tokbase + 2 * DMODEL + h * DHEAD;
    const bf16* vlp = qkvl + tokbase + 2 * DMODEL + h * DHEAD;

#pragma unroll
    for (int it = 0; it < 4; it++) {
        int idx = tid + it * 256;
        int row = idx >> 3, seg = idx & 7;
        uint32_t off = SW128((uint32_t)(row * 128 + seg * 16));
        size_t g = (size_t)row * QKVW + seg * 8;
        cp16(sq + off,         qhp + g);
        cp16(sq + 16384 + off, qlp + g);
    }
    CP_COMMIT();
    attn_stage_kv(sstage, khp, klp, vhp, vlp, tid);
    CP_COMMIT();

    float o[8][4];
#pragma unroll
    for (int d = 0; d < 8; d++)
#pragma unroll
        for (int q = 0; q < 4; q++) o[d][q] = 0.f;
    float m0 = NEGINF, m1 = NEGINF, l0 = 0.f, l1 = 0.f;

    int ar = lane & 15, ahalf = lane >> 4;
    int brow = (lane & 7) + ((lane >> 4) << 3);
    int bhalf = (lane >> 3) & 1;
    int vkrow = (lane & 7) + (((lane >> 3) & 1) << 3);
    int vncol = (lane >> 4) * 8;
    int r0g = q0 + wid * 16 + (lane >> 2);

    int nkt = 2 * qt + 2;
    for (int kt = 0; kt < nkt; kt++) {
        __syncthreads();
        if (kt + 1 < nkt) {
            attn_stage_kv(sstage + (uint32_t)((kt + 1) & 1) * ASTG,
                          khp + (size_t)(kt + 1) * 64 * QKVW, klp + (size_t)(kt + 1) * 64 * QKVW,
                          vhp + (size_t)(kt + 1) * 64 * QKVW, vlp + (size_t)(kt + 1) * 64 * QKVW, tid);
            CP_COMMIT();
            CP_WAIT(1);
        } else {
            CP_WAIT(0);
        }
        __syncthreads();
        uint32_t kb = sstage + (uint32_t)(kt & 1) * ASTG;

        float s[8][4];
#pragma unroll
        for (int ni = 0; ni < 8; ni++)
#pragma unroll
            for (int q = 0; q < 4; q++) s[ni][q] = 0.f;
#pragma unroll
        for (int ks = 0; ks < 4; ks++) {
            uint32_t ah[4], al[4];
            uint32_t offa = SW128((uint32_t)((wid * 16 + ar) * 128 + ks * 32 + ahalf * 16));
            LDSM4(ah[0], ah[1], ah[2], ah[3], sq + offa);
            LDSM4(al[0], al[1], al[2], al[3], sq + 16384 + offa);
#pragma unroll
            for (int nb = 0; nb < 4; nb++) {
                uint32_t bh[4], bl[4];
                uint32_t offb = SW128((uint32_t)((nb * 16 + brow) * 128 + ks * 32 + bhalf * 16));
                LDSM4(bh[0], bh[1], bh[2], bh[3], kb + offb);
                LDSM4(bl[0], bl[1], bl[2], bl[3], kb + 8192 + offb);
#pragma unroll
                for (int niL = 0; niL < 2; niL++) {
                    int ni = nb * 2 + niL, p = niL * 2;
                    MMA16816(s[ni], ah, bh[p], bh[p + 1]);
                    MMA16816(s[ni], ah, bl[p], bl[p + 1]);
                    MMA16816(s[ni], al, bh[p], bh[p + 1]);
                }
            }
        }

        if (kt >= 2 * qt) {
            int cbase = kt * 64 + (lane & 3) * 2;
#pragma unroll
            for (int ni = 0; ni < 8; ni++) {
                int c0 = cbase + ni * 8, c1 = c0 + 1;
                if (c0 > r0g)     s[ni][0] = NEGINF;
                if (c1 > r0g)     s[ni][1] = NEGINF;
                if (c0 > r0g + 8) s[ni][2] = NEGINF;
                if (c1 > r0g + 8) s[ni][3] = NEGINF;
            }
        }

        float tm0 = NEGINF, tm1 = NEGINF;
#pragma unroll
        for (int ni = 0; ni < 8; ni++) {
            tm0 = fmaxf(tm0, fmaxf(s[ni][0], s[ni][1]));
            tm1 = fmaxf(tm1, fmaxf(s[ni][2], s[ni][3]));
        }
        tm0 = fmaxf(tm0, __shfl_xor_sync(0xffffffffu, tm0, 1));
        tm0 = fmaxf(tm0, __shfl_xor_sync(0xffffffffu, tm0, 2));
        tm1 = fmaxf(tm1, __shfl_xor_sync(0xffffffffu, tm1, 1));
        tm1 = fmaxf(tm1, __shfl_xor_sync(0xffffffffu, tm1, 2));
        float nm0 = fmaxf(m0, tm0), nm1 = fmaxf(m1, tm1);
        float alpha0 = __expf(m0 - nm0), alpha1 = __expf(m1 - nm1);
        m0 = nm0; m1 = nm1;
        float rs0 = 0.f, rs1 = 0.f;
#pragma unroll
        for (int ni = 0; ni < 8; ni++) {
            s[ni][0] = __expf(s[ni][0] - nm0);
            s[ni][1] = __expf(s[ni][1] - nm0);
            s[ni][2] = __expf(s[ni][2] - nm1);
            s[ni][3] = __expf(s[ni][3] - nm1);
            rs0 += s[ni][0] + s[ni][1];
            rs1 += s[ni][2] + s[ni][3];
        }
        rs0 += __shfl_xor_sync(0xffffffffu, rs0, 1);
        rs0 += __shfl_xor_sync(0xffffffffu, rs0, 2);
        rs1 += __shfl_xor_sync(0xffffffffu, rs1, 1);
        rs1 += __shfl_xor_sync(0xffffffffu, rs1, 2);
        l0 = l0 * alpha0 + rs0;
        l1 = l1 * alpha1 + rs1;
#pragma unroll
        for (int d = 0; d < 8; d++) {
            o[d][0] *= alpha0; o[d][1] *= alpha0;
            o[d][2] *= alpha1; o[d][3] *= alpha1;
        }

#pragma unroll
        for (int ks = 0; ks < 4; ks++) {
            uint32_t pa_h[4], pa_l[4];
            pa_h[0] = pack_hi2(s[2 * ks][0], s[2 * ks][1]);
            pa_h[1] = pack_hi2(s[2 * ks][2], s[2 * ks][3]);
            pa_h[2] = pack_hi2(s[2 * ks + 1][0], s[2 * ks + 1][1]);
            pa_h[3] = pack_hi2(s[2 * ks + 1][2], s[2 * ks + 1][3]);
            pa_l[0] = pack_lo2(s[2 * ks][0], s[2 * ks][1]);
            pa_l[1] = pack_lo2(s[2 * ks][2], s[2 * ks][3]);
            pa_l[2] = pack_lo2(s[2 * ks + 1][0], s[2 * ks + 1][1]);
            pa_l[3] = pack_lo2(s[2 * ks + 1][2], s[2 * ks + 1][3]);
#pragma unroll
            for (int nb = 0; nb < 4; nb++) {
                uint32_t vh[4], vl[4];
                uint32_t offv = SW128((uint32_t)((ks * 16 + vkrow) * 128 + nb * 32 + vncol * 2));
                LDSM4T(vh[0], vh[1], vh[2], vh[3], kb + 16384 + offv);
                LDSM4T(vl[0], vl[1], vl[2], vl[3], kb + 24576 + offv);
#pragma unroll
                for (int niL = 0; niL < 2; niL++) {
                    int d = nb * 2 + niL, p = niL * 2;
                    MMA16816(o[d], pa_h, vh[p], vh[p + 1]);
                    MMA16816(o[d], pa_h, vl[p], vl[p + 1]);
                    MMA16816(o[d], pa_l, vh[p], vh[p + 1]);
                }
            }
        }
    }

    // epilogue -> z f32 (tf32-rounded for O-proj GEMM)
    float inv0 = 1.0f / l0, inv1 = 1.0f / l1;
    size_t rb0 = ((size_t)b * SEQ + q0 + wid * 16 + (lane >> 2)) * DMODEL + h * DHEAD + (lane & 3) * 2;
    size_t rb1 = rb0 + 8 * DMODEL;
#pragma unroll
    for (int d = 0; d < 8; d++) {
        *(float2*)&z[rb0 + d * 8] = make_float2(to_tf32(o[d][0] * inv0), to_tf32(o[d][1] * inv0));
        *(float2*)&z[rb1 + d * 8] = make_float2(to_tf32(o[d][2] * inv1), to_tf32(o[d][3] * inv1));
    }
}

// ---------------- launch ----------------
extern "C" void kernel_launch(void* const* d_in, const int* in_sizes, int n_in,
                              void* d_out, int out_size) {
    const float* resid_pre = (const float*)d_in[0];
    const float* WQ  = (const float*)d_in[1];
    const float* WK  = (const float*)d_in[2];
    const float* WV  = (const float*)d_in[3];
    const float* WO  = (const float*)d_in[4];
    const float* bQ  = (const float*)d_in[5];
    const float* bK  = (const float*)d_in[6];
    const float* bV  = (const float*)d_in[7];
    const float* bO  = (const float*)d_in[8];
    const float* ln1w = (const float*)d_in[9];
    const float* ln1b = (const float*)d_in[10];
    const float* ln2w = (const float*)d_in[11];
    const float* ln2b = (const float*)d_in[12];
    const float* Win  = (const float*)d_in[13];
    const float* bin  = (const float*)d_in[14];
    const float* Wout = (const float*)d_in[15];
    const float* bout = (const float*)d_in[16];
    float* out = (float*)d_out;

    float *p_xn, *p_xn2, *p_z, *p_hid, *p_wqkv, *p_wo, *p_win, *p_wout, *p_bqkv, *p_mid;
    bf16 *p_qkvh, *p_qkvl;
    cudaGetSymbolAddress((void**)&p_xn, g_xn);
    cudaGetSymbolAddress((void**)&p_xn2, g_xn2);
    cudaGetSymbolAddress((void**)&p_z, g_z);
    cudaGetSymbolAddress((void**)&p_hid, g_hid);
    cudaGetSymbolAddress((void**)&p_qkvh, g_qkv_hi);
    cudaGetSymbolAddress((void**)&p_qkvl, g_qkv_lo);
    cudaGetSymbolAddress((void**)&p_wqkv, g_wqkv);
    cudaGetSymbolAddress((void**)&p_wo, g_wo);
    cudaGetSymbolAddress((void**)&p_win, g_win);
    cudaGetSymbolAddress((void**)&p_wout, g_wout);
    cudaGetSymbolAddress((void**)&p_bqkv, g_bqkv);
    cudaGetSymbolAddress((void**)&p_mid, g_mid);

    cudaFuncSetAttribute(attn_mma, cudaFuncAttributeMaxDynamicSharedMemorySize, ASMEM);
    cudaFuncSetAttribute(gemm_tf32<1>, cudaFuncAttributeMaxDynamicSharedMemorySize, TSMEM);
    cudaFuncSetAttribute(gemm_tf32<2>, cudaFuncAttributeMaxDynamicSharedMemorySize, TSMEM);
    cudaFuncSetAttribute(gemm_tf32<3>, cudaFuncAttributeMaxDynamicSharedMemorySize, TSMEM);

    // 1) weight packs (tf32-rounded; W_Q scaled by 1/8)
    pack_T<<<dim3(2, 24, 12), 256>>>(WQ, p_wqkv, DMODEL, DHEAD,
                                     (long)DMODEL * DHEAD, (long)DHEAD * DMODEL, 0.125f);
    pack_T<<<dim3(2, 24, 12), 256>>>(WK, p_wqkv + DMODEL * DMODEL,
                                     DMODEL, DHEAD, (long)DMODEL * DHEAD, (long)DHEAD * DMODEL, 1.0f);
    pack_T<<<dim3(2, 24, 12), 256>>>(WV, p_wqkv + 2 * DMODEL * DMODEL,
                                     DMODEL, DHEAD, (long)DMODEL * DHEAD, (long)DHEAD * DMODEL, 1.0f);
    pack_T<<<dim3(24, 24, 1), 256>>>(WO, p_wo, DMODEL, DMODEL, 0, 0, 1.0f);
    pack_T<<<dim3(96, 24, 1), 256>>>(Win, p_win, DMODEL, DMLP, 0, 0, 1.0f);
    pack_T<<<dim3(24, 96, 1), 256>>>(Wout, p_wout, DMLP, DMODEL, 0, 0, 1.0f);
    pack_bqkv_kernel<<<(QKVW + 255) / 256, 256>>>(bQ, bK, bV);

    // 2) LN1 -> tf32 f32
    ln_kernel<<<MTOT, 256>>>(resid_pre, ln1w, ln1b, p_xn);

    // 3) QKV projection (tf32) -> bf16 hi/lo for attention
    gemm_tf32<3><<<dim3(QKVW / 128, MTOT / 128), 256, TSMEM>>>(
        p_xn, p_wqkv, p_bqkv, nullptr, nullptr, p_qkvh, p_qkvl, QKVW, DMODEL, DMODEL / 32);

    // 4) causal flash attention (split-bf16 tensor cores) -> z tf32 f32
    attn_mma<<<dim3(SEQ / 128, NHEADS, BATCH), 256, ASMEM>>>(p_qkvh, p_qkvl, p_z);

    // 5) O projection + residual (tf32) -> resid_mid f32
    gemm_tf32<2><<<dim3(DMODEL / 128, MTOT / 128), 256, TSMEM>>>(
        p_z, p_wo, bO, resid_pre, p_mid, nullptr, nullptr, DMODEL, DMODEL, DMODEL / 32);

    // 6) LN2 -> tf32 f32
    ln_kernel<<<MTOT, 256>>>(p_mid, ln2w, ln2b, p_xn2);

    // 7) MLP in + GELU (tf32) -> hidden tf32 f32
    gemm_tf32<1><<<dim3(DMLP / 128, MTOT / 128), 256, TSMEM>>>(
        p_xn2, p_win, bin, nullptr, p_hid, nullptr, nullptr, DMLP, DMODEL, DMODEL / 32);

    // 8) MLP out + residual (tf32) -> out f32
    gemm_tf32<2><<<dim3(DMODEL / 128, MTOT / 128), 256, TSMEM>>>(
        p_hid, p_wout, bout, p_mid, out, nullptr, nullptr, DMODEL, DMLP, DMLP / 32);
}